// round 7
// baseline (speedup 1.0000x reference)
#include <cuda_runtime.h>
#include <cuda_fp16.h>
#include <cstdint>

// Problem constants
#define TOK   65536      // B*S = 8*8192
#define DM    512
#define DQKV  1536
#define DFF   2048
#define NHEAD 8
#define DH    64
#define WIN   32
#define NWIN  2048       // TOK/WIN
#define EPSLN 1e-5f

// ---------------------------------------------------------------------------
// Scratch (device globals; allocation-free per harness rules)
// ---------------------------------------------------------------------------
__device__ __half g_xh  [(size_t)TOK * DM];
__device__ __half g_qkvh[(size_t)TOK * DQKV];
__device__ __half g_oh  [(size_t)TOK * DM];
__device__ __half g_x1h [(size_t)TOK * DM];
__device__ __half g_hh  [(size_t)TOK * DFF];
__device__ float  g_f32a[(size_t)TOK * DM];   // x+attn_out, then x1+ff_out
__device__ float  g_x1  [(size_t)TOK * DM];
// Transposed (N-major) fp16 weights
__device__ __half g_wqkvt[(size_t)DQKV * DM];
__device__ __half g_wot  [DM * DM];
__device__ __half g_w1t  [(size_t)DFF * DM];
__device__ __half g_w2t  [(size_t)DM * DFF];
__device__ float  g_bqkv [DQKV];

// ---------------------------------------------------------------------------
// fp32 -> fp16 convert
// ---------------------------------------------------------------------------
__global__ void f2h_kernel(const float* __restrict__ x, __half* __restrict__ xh)
{
    size_t i = (size_t)blockIdx.x * blockDim.x + threadIdx.x;
    float4 v = ((const float4*)x)[i];
    __half2 h0 = __floats2half2_rn(v.x, v.y);
    __half2 h1 = __floats2half2_rn(v.z, v.w);
    uint2 u;
    u.x = *(uint32_t*)&h0;
    u.y = *(uint32_t*)&h1;
    ((uint2*)xh)[i] = u;
}

__global__ void bias_concat_kernel(const float* __restrict__ bq,
                                   const float* __restrict__ bk,
                                   const float* __restrict__ bv,
                                   float* __restrict__ bqkv)
{
    int i = blockIdx.x * blockDim.x + threadIdx.x;
    const float* src = (i < DM) ? bq : (i < 2 * DM) ? bk : bv;
    bqkv[i] = src[i & (DM - 1)];
}

// ---------------------------------------------------------------------------
// Weight transpose with fp16 rounding: W[K,N] fp32 -> Wt[N,K] fp16
// ---------------------------------------------------------------------------
__global__ void transpose_h_kernel(const float* __restrict__ W,
                                   __half* __restrict__ Wt, int K, int N)
{
    __shared__ float t[32][33];
    const int n0 = blockIdx.x * 32, k0 = blockIdx.y * 32;
    const int tx = threadIdx.x, ty = threadIdx.y;
#pragma unroll
    for (int i = ty; i < 32; i += 8)
        t[i][tx] = W[(size_t)(k0 + i) * N + n0 + tx];
    __syncthreads();
#pragma unroll
    for (int i = ty; i < 32; i += 8)
        Wt[(size_t)(n0 + i) * K + k0 + tx] = __float2half_rn(t[tx][i]);
}

// ---------------------------------------------------------------------------
// FP16 tensor-core GEMM: C[M,N] = A[M,K] @ Bt[N,K]^T + bias (+residual, ReLU)
// CTA tile 128x256, BK=64 halfs, 256 threads = 8 warps of 64x64,
// double-buffered cp.async in dynamic smem, ldmatrix, mma.sync.m16n8k16.
// ---------------------------------------------------------------------------
#define GBK 64
#define HSTRIDE 72                         // halfs per smem row (64 data + 8 pad)
#define ABUF (128 * HSTRIDE * 2)           // 18432 B
#define BBUF (256 * HSTRIDE * 2)           // 36864 B
#define STGB (ABUF + BBUF)                 // 55296 B per stage
#define GEMM_SMEM (2 * STGB)               // 110592 B

__device__ __forceinline__ void ldsm_x4(uint32_t r[4], uint32_t addr)
{
    asm volatile("ldmatrix.sync.aligned.m8n8.x4.shared.b16 {%0,%1,%2,%3}, [%4];"
                 : "=r"(r[0]), "=r"(r[1]), "=r"(r[2]), "=r"(r[3]) : "r"(addr));
}

__device__ __forceinline__ void mma_f16(float c[4], const uint32_t a[4],
                                        const uint32_t b[2])
{
    asm volatile(
        "mma.sync.aligned.m16n8k16.row.col.f32.f16.f16.f32 "
        "{%0,%1,%2,%3}, {%4,%5,%6,%7}, {%8,%9}, {%0,%1,%2,%3};"
        : "+f"(c[0]), "+f"(c[1]), "+f"(c[2]), "+f"(c[3])
        : "r"(a[0]), "r"(a[1]), "r"(a[2]), "r"(a[3]), "r"(b[0]), "r"(b[1]));
}

__device__ __forceinline__ void cp16(uint32_t smem, const __half* gmem)
{
    asm volatile("cp.async.cg.shared.global [%0], [%1], 16;"
                 :: "r"(smem), "l"(gmem));
}

__global__ __launch_bounds__(256, 1) void h16_gemm_kernel(
    const __half* __restrict__ A, const __half* __restrict__ Bt,
    const float* __restrict__ bias, const float* __restrict__ Radd,
    float* __restrict__ Cf, __half* __restrict__ Ch,
    int M, int N, int K, int relu)
{
    extern __shared__ __half smem_dyn[];

    const int tid = threadIdx.x;
    const int bm = blockIdx.y, bn = blockIdx.x;
    const int wid = tid >> 5, lane = tid & 31;
    const int warp_m = wid & 1;          // 2 m-warps * 64 rows
    const int warp_n = wid >> 1;         // 4 n-warps * 64 cols
    const int gid = lane >> 2, ctid = lane & 3;
    const int mat = lane >> 3, rin = lane & 7;

    const uint32_t s_base = (uint32_t)__cvta_generic_to_shared(smem_dyn);

    // cp.async indices
    int arow[4], acol[4];                // A: 1024 chunks, 4/thread
#pragma unroll
    for (int i = 0; i < 4; i++) {
        int c = tid + i * 256;
        arow[i] = c >> 3;
        acol[i] = (c & 7) * 8;
    }
    int brow[8], bcol[8];                // B: 2048 chunks, 8/thread
#pragma unroll
    for (int i = 0; i < 8; i++) {
        int c = tid + i * 256;
        brow[i] = c >> 3;
        bcol[i] = (c & 7) * 8;
    }

    // ldmatrix per-lane byte offsets (within a stage), excluding k-step
    uint32_t a_off[4], b_off[4];
#pragma unroll
    for (int mt = 0; mt < 4; mt++)
        a_off[mt] = ((warp_m * 64 + mt * 16 + (mat & 1) * 8 + rin) * HSTRIDE
                     + (mat >> 1) * 8) * 2;
#pragma unroll
    for (int ntp = 0; ntp < 4; ntp++)
        b_off[ntp] = ((warp_n * 64 + ntp * 16 + (mat >> 1) * 8 + rin) * HSTRIDE
                      + (mat & 1) * 8) * 2;

    float acc[4][8][4];
#pragma unroll
    for (int mt = 0; mt < 4; mt++)
#pragma unroll
        for (int nt = 0; nt < 8; nt++)
#pragma unroll
            for (int i = 0; i < 4; i++) acc[mt][nt][i] = 0.0f;

    const __half* Abase = A  + (size_t)(bm * 128) * K;
    const __half* Bbase = Bt + (size_t)(bn * 256) * K;
    const int ntiles = K / GBK;

    auto load_tile = [&](int stage, int t) {
        const __half* Ap = Abase + t * GBK;
        const __half* Bp = Bbase + t * GBK;
        const uint32_t as = s_base + (uint32_t)stage * STGB;
        const uint32_t bs = as + ABUF;
#pragma unroll
        for (int i = 0; i < 4; i++)
            cp16(as + (arow[i] * HSTRIDE + acol[i]) * 2,
                 Ap + (size_t)arow[i] * K + acol[i]);
#pragma unroll
        for (int i = 0; i < 8; i++)
            cp16(bs + (brow[i] * HSTRIDE + bcol[i]) * 2,
                 Bp + (size_t)brow[i] * K + bcol[i]);
    };

    // Prologue: tile 0 -> stage 0
    load_tile(0, 0);
    asm volatile("cp.async.commit_group;");

    for (int t = 0; t < ntiles; t++) {
        const int buf = t & 1;
        if (t + 1 < ntiles) {
            load_tile(buf ^ 1, t + 1);
            asm volatile("cp.async.commit_group;");
            asm volatile("cp.async.wait_group 1;");
        } else {
            asm volatile("cp.async.wait_group 0;");
        }
        __syncthreads();

        const uint32_t as = s_base + (uint32_t)buf * STGB;
        const uint32_t bs = as + ABUF;
#pragma unroll
        for (int ks = 0; ks < 4; ks++) {
            const uint32_t kkb = ks * 32;   // 16 halfs * 2B
            uint32_t af[4][4];
#pragma unroll
            for (int mt = 0; mt < 4; mt++)
                ldsm_x4(af[mt], as + a_off[mt] + kkb);
            uint32_t bf[8][2];
#pragma unroll
            for (int ntp = 0; ntp < 4; ntp++) {
                uint32_t qd[4];
                ldsm_x4(qd, bs + b_off[ntp] + kkb);
                bf[2 * ntp][0]     = qd[0]; bf[2 * ntp][1]     = qd[1];
                bf[2 * ntp + 1][0] = qd[2]; bf[2 * ntp + 1][1] = qd[3];
            }
#pragma unroll
            for (int mt = 0; mt < 4; mt++)
#pragma unroll
                for (int nt = 0; nt < 8; nt++)
                    mma_f16(acc[mt][nt], af[mt], bf[nt]);
        }
        __syncthreads();
    }

    // Epilogue: bias (+residual, +ReLU) -> fp32 or fp16 output
#pragma unroll
    for (int mt = 0; mt < 4; mt++) {
        const int r0 = bm * 128 + warp_m * 64 + mt * 16 + gid;
#pragma unroll
        for (int nt = 0; nt < 8; nt++) {
            const int col = bn * 256 + warp_n * 64 + nt * 8 + 2 * ctid;
            const float b0 = bias[col], b1 = bias[col + 1];
            float2 v0, v1;
            v0.x = acc[mt][nt][0] + b0; v0.y = acc[mt][nt][1] + b1;
            v1.x = acc[mt][nt][2] + b0; v1.y = acc[mt][nt][3] + b1;
            const size_t base0 = (size_t)r0 * N + col;
            const size_t base1 = (size_t)(r0 + 8) * N + col;
            if (Radd) {
                float2 ra = *(const float2*)(Radd + base0);
                float2 rb = *(const float2*)(Radd + base1);
                v0.x += ra.x; v0.y += ra.y;
                v1.x += rb.x; v1.y += rb.y;
            }
            if (relu) {
                v0.x = fmaxf(v0.x, 0.f); v0.y = fmaxf(v0.y, 0.f);
                v1.x = fmaxf(v1.x, 0.f); v1.y = fmaxf(v1.y, 0.f);
            }
            if (Cf) {
                *(float2*)(Cf + base0) = v0;
                *(float2*)(Cf + base1) = v1;
            } else {
                __half2 h0 = __floats2half2_rn(v0.x, v0.y);
                __half2 h1 = __floats2half2_rn(v1.x, v1.y);
                *(__half2*)(Ch + base0) = h0;
                *(__half2*)(Ch + base1) = h1;
            }
        }
    }
}

// ---------------------------------------------------------------------------
// Window attention (reads packed qkv [TOK, 1536], writes oh [TOK, 512])
// ---------------------------------------------------------------------------
__global__ __launch_bounds__(256) void window_attn_kernel(
    const __half* __restrict__ qkv, __half* __restrict__ o)
{
    const int bid = blockIdx.x;
    const int h = bid & (NHEAD - 1);
    const int w = bid >> 3;
    const int t0 = w * WIN;
    const int tid = threadIdx.x;

    __shared__ float qs[WIN][DH + 1];
    __shared__ float ks[WIN][DH + 1];
    __shared__ float vs[WIN][DH + 1];
    __shared__ float sc[WIN][WIN + 1];

    {
        const int row = tid >> 3;
        const int h8 = (tid & 7) * 8;
        const size_t base = (size_t)(t0 + row) * DQKV + h * DH + h8;
        uint4 uq = *(const uint4*)(qkv + base);
        uint4 uk = *(const uint4*)(qkv + base + DM);
        uint4 uv = *(const uint4*)(qkv + base + 2 * DM);
        const __half2* hq = (const __half2*)&uq;
        const __half2* hk = (const __half2*)&uk;
        const __half2* hv = (const __half2*)&uv;
#pragma unroll
        for (int j = 0; j < 4; j++) {
            float2 fq = __half22float2(hq[j]);
            float2 fk = __half22float2(hk[j]);
            float2 fv = __half22float2(hv[j]);
            qs[row][h8 + 2 * j]     = fq.x; qs[row][h8 + 2 * j + 1] = fq.y;
            ks[row][h8 + 2 * j]     = fk.x; ks[row][h8 + 2 * j + 1] = fk.y;
            vs[row][h8 + 2 * j]     = fv.x; vs[row][h8 + 2 * j + 1] = fv.y;
        }
    }
    __syncthreads();

#pragma unroll
    for (int i = 0; i < 4; i++) {
        int lin = tid + i * 256;
        int r = lin >> 5, c = lin & 31;
        float s = 0.f;
#pragma unroll
        for (int d = 0; d < DH; d++) s += qs[r][d] * ks[c][d];
        sc[r][c] = s * 0.125f;
    }
    __syncthreads();

    if (tid < WIN) {
        float m = -1e30f;
#pragma unroll
        for (int j = 0; j < WIN; j++) m = fmaxf(m, sc[tid][j]);
        float sum = 0.f;
#pragma unroll
        for (int j = 0; j < WIN; j++) {
            float e = __expf(sc[tid][j] - m);
            sc[tid][j] = e;
            sum += e;
        }
        float inv = 1.0f / sum;
#pragma unroll
        for (int j = 0; j < WIN; j++) sc[tid][j] *= inv;
    }
    __syncthreads();

#pragma unroll
    for (int i = 0; i < 4; i++) {
        int lin = tid + i * 256;
        int r = lin >> 5, d2 = (lin & 31) * 2;
        float s0 = 0.f, s1 = 0.f;
#pragma unroll
        for (int j = 0; j < WIN; j++) {
            float a = sc[r][j];
            s0 += a * vs[j][d2];
            s1 += a * vs[j][d2 + 1];
        }
        *(__half2*)(o + (size_t)(t0 + r) * DM + h * DH + d2) =
            __floats2half2_rn(s0, s1);
    }
}

// ---------------------------------------------------------------------------
// LayerNorm over a pre-summed row. One block (128 threads) per token row.
// ---------------------------------------------------------------------------
__global__ __launch_bounds__(128) void ln_kernel(
    const float* __restrict__ xr,
    const float* __restrict__ g, const float* __restrict__ b,
    float* __restrict__ y, __half* __restrict__ yh)
{
    const int row = blockIdx.x;
    const int tid = threadIdx.x;

    float4 xv = ((const float4*)(xr + (size_t)row * DM))[tid];
    float v0 = xv.x, v1 = xv.y, v2 = xv.z, v3 = xv.w;

    __shared__ float red[4];
    float s = v0 + v1 + v2 + v3;
#pragma unroll
    for (int off = 16; off > 0; off >>= 1) s += __shfl_xor_sync(0xffffffffu, s, off);
    if ((tid & 31) == 0) red[tid >> 5] = s;
    __syncthreads();
    const float mu = (red[0] + red[1] + red[2] + red[3]) * (1.0f / DM);

    float d0 = v0 - mu, d1 = v1 - mu, d2 = v2 - mu, d3 = v3 - mu;
    float qsum = d0 * d0 + d1 * d1 + d2 * d2 + d3 * d3;
    __syncthreads();
#pragma unroll
    for (int off = 16; off > 0; off >>= 1) qsum += __shfl_xor_sync(0xffffffffu, qsum, off);
    if ((tid & 31) == 0) red[tid >> 5] = qsum;
    __syncthreads();
    const float var = (red[0] + red[1] + red[2] + red[3]) * (1.0f / DM);
    const float inv = rsqrtf(var + EPSLN);

    float4 gv = ((const float4*)g)[tid];
    float4 bv = ((const float4*)b)[tid];
    float4 out;
    out.x = d0 * inv * gv.x + bv.x;
    out.y = d1 * inv * gv.y + bv.y;
    out.z = d2 * inv * gv.z + bv.z;
    out.w = d3 * inv * gv.w + bv.w;
    ((float4*)(y + (size_t)row * DM))[tid] = out;
    if (yh) {
        __half2 h0 = __floats2half2_rn(out.x, out.y);
        __half2 h1 = __floats2half2_rn(out.z, out.w);
        uint2 u;
        u.x = *(uint32_t*)&h0;
        u.y = *(uint32_t*)&h1;
        ((uint2*)(yh + (size_t)row * DM))[tid] = u;
    }
}

// ---------------------------------------------------------------------------
// Launch
// ---------------------------------------------------------------------------
extern "C" void kernel_launch(void* const* d_in, const int* in_sizes, int n_in,
                              void* d_out, int out_size)
{
    (void)in_sizes; (void)n_in; (void)out_size;
    const float* x   = (const float*)d_in[0];
    const float* Wq  = (const float*)d_in[1];
    const float* bq  = (const float*)d_in[2];
    const float* Wk  = (const float*)d_in[3];
    const float* bk  = (const float*)d_in[4];
    const float* Wv  = (const float*)d_in[5];
    const float* bv  = (const float*)d_in[6];
    const float* Wo  = (const float*)d_in[7];
    const float* bo  = (const float*)d_in[8];
    const float* g1  = (const float*)d_in[9];
    const float* be1 = (const float*)d_in[10];
    const float* W1  = (const float*)d_in[11];
    const float* b1  = (const float*)d_in[12];
    const float* W2  = (const float*)d_in[13];
    const float* b2  = (const float*)d_in[14];
    const float* g2  = (const float*)d_in[15];
    const float* be2 = (const float*)d_in[16];
    float* out = (float*)d_out;

    __half *xh, *qkvh, *oh, *x1h, *hh;
    float *f32a, *x1, *bqkv;
    __half *wqkvt, *wot, *w1t, *w2t;
    cudaGetSymbolAddress((void**)&xh,    g_xh);
    cudaGetSymbolAddress((void**)&qkvh,  g_qkvh);
    cudaGetSymbolAddress((void**)&oh,    g_oh);
    cudaGetSymbolAddress((void**)&x1h,   g_x1h);
    cudaGetSymbolAddress((void**)&hh,    g_hh);
    cudaGetSymbolAddress((void**)&f32a,  g_f32a);
    cudaGetSymbolAddress((void**)&x1,    g_x1);
    cudaGetSymbolAddress((void**)&wqkvt, g_wqkvt);
    cudaGetSymbolAddress((void**)&wot,   g_wot);
    cudaGetSymbolAddress((void**)&w1t,   g_w1t);
    cudaGetSymbolAddress((void**)&w2t,   g_w2t);
    cudaGetSymbolAddress((void**)&bqkv,  g_bqkv);

    cudaFuncSetAttribute(h16_gemm_kernel,
                         cudaFuncAttributeMaxDynamicSharedMemorySize, GEMM_SMEM);

    // Convert x; transpose+convert weights; concat qkv bias
    f2h_kernel<<<(TOK * DM / 4) / 256, 256>>>(x, xh);
    {
        dim3 b(32, 8);
        transpose_h_kernel<<<dim3(DM / 32,  DM / 32),  b>>>(Wq, wqkvt,             DM,  DM);
        transpose_h_kernel<<<dim3(DM / 32,  DM / 32),  b>>>(Wk, wqkvt + 512 * DM,  DM,  DM);
        transpose_h_kernel<<<dim3(DM / 32,  DM / 32),  b>>>(Wv, wqkvt + 1024 * DM, DM,  DM);
        transpose_h_kernel<<<dim3(DM / 32,  DM / 32),  b>>>(Wo, wot, DM,  DM);
        transpose_h_kernel<<<dim3(DFF / 32, DM / 32),  b>>>(W1, w1t, DM,  DFF);
        transpose_h_kernel<<<dim3(DM / 32,  DFF / 32), b>>>(W2, w2t, DFF, DM);
        bias_concat_kernel<<<DQKV / 256, 256>>>(bq, bk, bv, bqkv);
    }

    dim3 gQKV(DQKV / 256, TOK / 128);  // (6, 512)
    dim3 gD  (DM   / 256, TOK / 128);  // (2, 512)
    dim3 gFF (DFF  / 256, TOK / 128);  // (8, 512)

    // Fused QKV projection -> qkvh [TOK, 1536] (fp16)
    h16_gemm_kernel<<<gQKV, 256, GEMM_SMEM>>>(xh, wqkvt, bqkv, nullptr,
                                              nullptr, qkvh, TOK, DQKV, DM, 0);

    // Block-local window attention
    window_attn_kernel<<<NWIN * NHEAD, 256>>>(qkvh, oh);

    // Output projection + residual(x) -> f32a = x + attn_out
    h16_gemm_kernel<<<gD, 256, GEMM_SMEM>>>(oh, wot, bo, x,
                                            f32a, nullptr, TOK, DM, DM, 0);

    // LN1 -> x1 (fp32) + x1h (fp16)
    ln_kernel<<<TOK, 128>>>(f32a, g1, be1, x1, x1h);

    // FFN
    h16_gemm_kernel<<<gFF, 256, GEMM_SMEM>>>(x1h, w1t, b1, nullptr,
                                             nullptr, hh, TOK, DFF, DM, 1);
    // W2 + residual(x1) -> f32a = x1 + ff_out
    h16_gemm_kernel<<<gD, 256, GEMM_SMEM>>>(hh, w2t, b2, x1,
                                            f32a, nullptr, TOK, DM, DFF, 0);

    // LN2 -> output (fp32)
    ln_kernel<<<TOK, 128>>>(f32a, g2, be2, out, nullptr);
}

// round 8
// speedup vs baseline: 1.0368x; 1.0368x over previous
#include <cuda_runtime.h>
#include <cuda_fp16.h>
#include <cstdint>

// Problem constants
#define TOK   65536      // B*S = 8*8192
#define DM    512
#define DQKV  1536
#define DFF   2048
#define NHEAD 8
#define DH    64
#define WIN   32
#define NWIN  2048       // TOK/WIN
#define EPSLN 1e-5f

// ---------------------------------------------------------------------------
// Scratch (device globals; allocation-free per harness rules)
// ---------------------------------------------------------------------------
__device__ __half g_xh  [(size_t)TOK * DM];
__device__ __half g_qkvh[(size_t)TOK * DQKV];
__device__ __half g_oh  [(size_t)TOK * DM];
__device__ __half g_x1h [(size_t)TOK * DM];
__device__ __half g_hh  [(size_t)TOK * DFF];
__device__ float  g_f32a[(size_t)TOK * DM];   // x+attn_out, then x1+ff_out
__device__ float  g_x1  [(size_t)TOK * DM];
// Transposed (N-major) fp16 weights
__device__ __half g_wqkvt[(size_t)DQKV * DM];
__device__ __half g_wot  [DM * DM];
__device__ __half g_w1t  [(size_t)DFF * DM];
__device__ __half g_w2t  [(size_t)DM * DFF];
__device__ float  g_bqkv [DQKV];

// ---------------------------------------------------------------------------
// fp32 -> fp16 convert
// ---------------------------------------------------------------------------
__global__ void f2h_kernel(const float* __restrict__ x, __half* __restrict__ xh)
{
    size_t i = (size_t)blockIdx.x * blockDim.x + threadIdx.x;
    float4 v = ((const float4*)x)[i];
    __half2 h0 = __floats2half2_rn(v.x, v.y);
    __half2 h1 = __floats2half2_rn(v.z, v.w);
    uint2 u;
    u.x = *(uint32_t*)&h0;
    u.y = *(uint32_t*)&h1;
    ((uint2*)xh)[i] = u;
}

__global__ void bias_concat_kernel(const float* __restrict__ bq,
                                   const float* __restrict__ bk,
                                   const float* __restrict__ bv,
                                   float* __restrict__ bqkv)
{
    int i = blockIdx.x * blockDim.x + threadIdx.x;
    const float* src = (i < DM) ? bq : (i < 2 * DM) ? bk : bv;
    bqkv[i] = src[i & (DM - 1)];
}

// ---------------------------------------------------------------------------
// Weight transpose with fp16 rounding: W[K,N] fp32 -> Wt[N,K] fp16
// ---------------------------------------------------------------------------
__global__ void transpose_h_kernel(const float* __restrict__ W,
                                   __half* __restrict__ Wt, int K, int N)
{
    __shared__ float t[32][33];
    const int n0 = blockIdx.x * 32, k0 = blockIdx.y * 32;
    const int tx = threadIdx.x, ty = threadIdx.y;
#pragma unroll
    for (int i = ty; i < 32; i += 8)
        t[i][tx] = W[(size_t)(k0 + i) * N + n0 + tx];
    __syncthreads();
#pragma unroll
    for (int i = ty; i < 32; i += 8)
        Wt[(size_t)(n0 + i) * K + k0 + tx] = __float2half_rn(t[tx][i]);
}

// ---------------------------------------------------------------------------
// FP16 tensor-core GEMM: C[M,N] = A[M,K] @ Bt[N,K]^T + bias (+residual, ReLU)
// CTA tile 128x128, BK=64 halfs, 256 threads (8 warps of 32x64),
// 3-stage cp.async ring in dynamic smem, ldmatrix, mma.sync.m16n8k16.
// ---------------------------------------------------------------------------
#define GBK 64
#define HSTRIDE 72                         // halfs per smem row (64 data + 8 pad)
#define OPBUF (128 * HSTRIDE * 2)          // 18432 B per operand per stage
#define STGB  (2 * OPBUF)                  // 36864 B per stage (A + B)
#define NSTG  3
#define GEMM_SMEM (NSTG * STGB)            // 110592 B

__device__ __forceinline__ void ldsm_x4(uint32_t r[4], uint32_t addr)
{
    asm volatile("ldmatrix.sync.aligned.m8n8.x4.shared.b16 {%0,%1,%2,%3}, [%4];"
                 : "=r"(r[0]), "=r"(r[1]), "=r"(r[2]), "=r"(r[3]) : "r"(addr));
}

__device__ __forceinline__ void mma_f16(float c[4], const uint32_t a[4],
                                        const uint32_t b[2])
{
    asm volatile(
        "mma.sync.aligned.m16n8k16.row.col.f32.f16.f16.f32 "
        "{%0,%1,%2,%3}, {%4,%5,%6,%7}, {%8,%9}, {%0,%1,%2,%3};"
        : "+f"(c[0]), "+f"(c[1]), "+f"(c[2]), "+f"(c[3])
        : "r"(a[0]), "r"(a[1]), "r"(a[2]), "r"(a[3]), "r"(b[0]), "r"(b[1]));
}

__device__ __forceinline__ void cp16(uint32_t smem, const __half* gmem)
{
    asm volatile("cp.async.cg.shared.global [%0], [%1], 16;"
                 :: "r"(smem), "l"(gmem));
}

__global__ __launch_bounds__(256, 2) void h16_gemm_kernel(
    const __half* __restrict__ A, const __half* __restrict__ Bt,
    const float* __restrict__ bias, const float* __restrict__ Radd,
    float* __restrict__ Cf, __half* __restrict__ Ch,
    int M, int N, int K, int relu)
{
    extern __shared__ __half smem_dyn[];

    const int tid = threadIdx.x;
    const int bm = blockIdx.y, bn = blockIdx.x;
    const int wid = tid >> 5, lane = tid & 31;
    const int warp_m = wid & 3;          // 4 m-warps * 32 rows
    const int warp_n = wid >> 2;         // 2 n-warps * 64 cols
    const int gid = lane >> 2, ctid = lane & 3;
    const int mat = lane >> 3, rin = lane & 7;

    const uint32_t s_base = (uint32_t)__cvta_generic_to_shared(smem_dyn);

    // cp.async indices: 1024 16B-chunks per tile per operand, 4 per thread
    int ldr[4], ldc[4];
#pragma unroll
    for (int i = 0; i < 4; i++) {
        int c = tid + i * 256;
        ldr[i] = c >> 3;
        ldc[i] = (c & 7) * 8;
    }

    // ldmatrix per-lane byte offsets (within a stage), excluding k-step
    uint32_t a_off[2], b_off[4];
#pragma unroll
    for (int mt = 0; mt < 2; mt++)
        a_off[mt] = ((warp_m * 32 + mt * 16 + (mat & 1) * 8 + rin) * HSTRIDE
                     + (mat >> 1) * 8) * 2;
#pragma unroll
    for (int ntp = 0; ntp < 4; ntp++)
        b_off[ntp] = ((warp_n * 64 + ntp * 16 + (mat >> 1) * 8 + rin) * HSTRIDE
                      + (mat & 1) * 8) * 2;

    float acc[2][8][4];
#pragma unroll
    for (int mt = 0; mt < 2; mt++)
#pragma unroll
        for (int nt = 0; nt < 8; nt++)
#pragma unroll
            for (int i = 0; i < 4; i++) acc[mt][nt][i] = 0.0f;

    const __half* Abase = A  + (size_t)(bm * 128) * K;
    const __half* Bbase = Bt + (size_t)(bn * 128) * K;
    const int ntiles = K / GBK;

    auto load_tile = [&](int stage, int t) {
        const __half* Ap = Abase + t * GBK;
        const __half* Bp = Bbase + t * GBK;
        const uint32_t as = s_base + (uint32_t)stage * STGB;
        const uint32_t bs = as + OPBUF;
#pragma unroll
        for (int i = 0; i < 4; i++) {
            cp16(as + (ldr[i] * HSTRIDE + ldc[i]) * 2,
                 Ap + (size_t)ldr[i] * K + ldc[i]);
            cp16(bs + (ldr[i] * HSTRIDE + ldc[i]) * 2,
                 Bp + (size_t)ldr[i] * K + ldc[i]);
        }
    };

    // Prologue: tiles 0,1 -> stages 0,1
    load_tile(0, 0);
    asm volatile("cp.async.commit_group;");
    if (ntiles > 1) load_tile(1, 1);
    asm volatile("cp.async.commit_group;");

    for (int t = 0; t < ntiles; t++) {
        const int stage = t % NSTG;
        if (t + 2 < ntiles) load_tile((t + 2) % NSTG, t + 2);
        asm volatile("cp.async.commit_group;");
        asm volatile("cp.async.wait_group 2;");
        __syncthreads();

        const uint32_t as = s_base + (uint32_t)stage * STGB;
        const uint32_t bs = as + OPBUF;
#pragma unroll
        for (int ks = 0; ks < 4; ks++) {
            const uint32_t kkb = ks * 32;   // 16 halfs * 2B
            uint32_t af[2][4];
#pragma unroll
            for (int mt = 0; mt < 2; mt++)
                ldsm_x4(af[mt], as + a_off[mt] + kkb);
            uint32_t bf[8][2];
#pragma unroll
            for (int ntp = 0; ntp < 4; ntp++) {
                uint32_t qd[4];
                ldsm_x4(qd, bs + b_off[ntp] + kkb);
                bf[2 * ntp][0]     = qd[0]; bf[2 * ntp][1]     = qd[1];
                bf[2 * ntp + 1][0] = qd[2]; bf[2 * ntp + 1][1] = qd[3];
            }
#pragma unroll
            for (int mt = 0; mt < 2; mt++)
#pragma unroll
                for (int nt = 0; nt < 8; nt++)
                    mma_f16(acc[mt][nt], af[mt], bf[nt]);
        }
        __syncthreads();
    }

    // Epilogue: bias (+residual, +ReLU) -> fp32 or fp16 output
#pragma unroll
    for (int mt = 0; mt < 2; mt++) {
        const int r0 = bm * 128 + warp_m * 32 + mt * 16 + gid;
#pragma unroll
        for (int nt = 0; nt < 8; nt++) {
            const int col = bn * 128 + warp_n * 64 + nt * 8 + 2 * ctid;
            const float b0 = bias[col], b1 = bias[col + 1];
            float2 v0, v1;
            v0.x = acc[mt][nt][0] + b0; v0.y = acc[mt][nt][1] + b1;
            v1.x = acc[mt][nt][2] + b0; v1.y = acc[mt][nt][3] + b1;
            const size_t base0 = (size_t)r0 * N + col;
            const size_t base1 = (size_t)(r0 + 8) * N + col;
            if (Radd) {
                float2 ra = *(const float2*)(Radd + base0);
                float2 rb = *(const float2*)(Radd + base1);
                v0.x += ra.x; v0.y += ra.y;
                v1.x += rb.x; v1.y += rb.y;
            }
            if (relu) {
                v0.x = fmaxf(v0.x, 0.f); v0.y = fmaxf(v0.y, 0.f);
                v1.x = fmaxf(v1.x, 0.f); v1.y = fmaxf(v1.y, 0.f);
            }
            if (Cf) {
                *(float2*)(Cf + base0) = v0;
                *(float2*)(Cf + base1) = v1;
            } else {
                __half2 h0 = __floats2half2_rn(v0.x, v0.y);
                __half2 h1 = __floats2half2_rn(v1.x, v1.y);
                *(__half2*)(Ch + base0) = h0;
                *(__half2*)(Ch + base1) = h1;
            }
        }
    }
}

// ---------------------------------------------------------------------------
// Window attention (reads packed qkv [TOK, 1536], writes oh [TOK, 512])
// ---------------------------------------------------------------------------
__global__ __launch_bounds__(256) void window_attn_kernel(
    const __half* __restrict__ qkv, __half* __restrict__ o)
{
    const int bid = blockIdx.x;
    const int h = bid & (NHEAD - 1);
    const int w = bid >> 3;
    const int t0 = w * WIN;
    const int tid = threadIdx.x;

    __shared__ float qs[WIN][DH + 1];
    __shared__ float ks[WIN][DH + 1];
    __shared__ float vs[WIN][DH + 1];
    __shared__ float sc[WIN][WIN + 1];

    {
        const int row = tid >> 3;
        const int h8 = (tid & 7) * 8;
        const size_t base = (size_t)(t0 + row) * DQKV + h * DH + h8;
        uint4 uq = *(const uint4*)(qkv + base);
        uint4 uk = *(const uint4*)(qkv + base + DM);
        uint4 uv = *(const uint4*)(qkv + base + 2 * DM);
        const __half2* hq = (const __half2*)&uq;
        const __half2* hk = (const __half2*)&uk;
        const __half2* hv = (const __half2*)&uv;
#pragma unroll
        for (int j = 0; j < 4; j++) {
            float2 fq = __half22float2(hq[j]);
            float2 fk = __half22float2(hk[j]);
            float2 fv = __half22float2(hv[j]);
            qs[row][h8 + 2 * j]     = fq.x; qs[row][h8 + 2 * j + 1] = fq.y;
            ks[row][h8 + 2 * j]     = fk.x; ks[row][h8 + 2 * j + 1] = fk.y;
            vs[row][h8 + 2 * j]     = fv.x; vs[row][h8 + 2 * j + 1] = fv.y;
        }
    }
    __syncthreads();

#pragma unroll
    for (int i = 0; i < 4; i++) {
        int lin = tid + i * 256;
        int r = lin >> 5, c = lin & 31;
        float s = 0.f;
#pragma unroll
        for (int d = 0; d < DH; d++) s += qs[r][d] * ks[c][d];
        sc[r][c] = s * 0.125f;
    }
    __syncthreads();

    if (tid < WIN) {
        float m = -1e30f;
#pragma unroll
        for (int j = 0; j < WIN; j++) m = fmaxf(m, sc[tid][j]);
        float sum = 0.f;
#pragma unroll
        for (int j = 0; j < WIN; j++) {
            float e = __expf(sc[tid][j] - m);
            sc[tid][j] = e;
            sum += e;
        }
        float inv = 1.0f / sum;
#pragma unroll
        for (int j = 0; j < WIN; j++) sc[tid][j] *= inv;
    }
    __syncthreads();

#pragma unroll
    for (int i = 0; i < 4; i++) {
        int lin = tid + i * 256;
        int r = lin >> 5, d2 = (lin & 31) * 2;
        float s0 = 0.f, s1 = 0.f;
#pragma unroll
        for (int j = 0; j < WIN; j++) {
            float a = sc[r][j];
            s0 += a * vs[j][d2];
            s1 += a * vs[j][d2 + 1];
        }
        *(__half2*)(o + (size_t)(t0 + r) * DM + h * DH + d2) =
            __floats2half2_rn(s0, s1);
    }
}

// ---------------------------------------------------------------------------
// LayerNorm over a pre-summed row. One block (128 threads) per token row.
// ---------------------------------------------------------------------------
__global__ __launch_bounds__(128) void ln_kernel(
    const float* __restrict__ xr,
    const float* __restrict__ g, const float* __restrict__ b,
    float* __restrict__ y, __half* __restrict__ yh)
{
    const int row = blockIdx.x;
    const int tid = threadIdx.x;

    float4 xv = ((const float4*)(xr + (size_t)row * DM))[tid];
    float v0 = xv.x, v1 = xv.y, v2 = xv.z, v3 = xv.w;

    __shared__ float red[4];
    float s = v0 + v1 + v2 + v3;
#pragma unroll
    for (int off = 16; off > 0; off >>= 1) s += __shfl_xor_sync(0xffffffffu, s, off);
    if ((tid & 31) == 0) red[tid >> 5] = s;
    __syncthreads();
    const float mu = (red[0] + red[1] + red[2] + red[3]) * (1.0f / DM);

    float d0 = v0 - mu, d1 = v1 - mu, d2 = v2 - mu, d3 = v3 - mu;
    float qsum = d0 * d0 + d1 * d1 + d2 * d2 + d3 * d3;
    __syncthreads();
#pragma unroll
    for (int off = 16; off > 0; off >>= 1) qsum += __shfl_xor_sync(0xffffffffu, qsum, off);
    if ((tid & 31) == 0) red[tid >> 5] = qsum;
    __syncthreads();
    const float var = (red[0] + red[1] + red[2] + red[3]) * (1.0f / DM);
    const float inv = rsqrtf(var + EPSLN);

    float4 gv = ((const float4*)g)[tid];
    float4 bv = ((const float4*)b)[tid];
    float4 out;
    out.x = d0 * inv * gv.x + bv.x;
    out.y = d1 * inv * gv.y + bv.y;
    out.z = d2 * inv * gv.z + bv.z;
    out.w = d3 * inv * gv.w + bv.w;
    ((float4*)(y + (size_t)row * DM))[tid] = out;
    if (yh) {
        __half2 h0 = __floats2half2_rn(out.x, out.y);
        __half2 h1 = __floats2half2_rn(out.z, out.w);
        uint2 u;
        u.x = *(uint32_t*)&h0;
        u.y = *(uint32_t*)&h1;
        ((uint2*)(yh + (size_t)row * DM))[tid] = u;
    }
}

// ---------------------------------------------------------------------------
// Launch
// ---------------------------------------------------------------------------
extern "C" void kernel_launch(void* const* d_in, const int* in_sizes, int n_in,
                              void* d_out, int out_size)
{
    (void)in_sizes; (void)n_in; (void)out_size;
    const float* x   = (const float*)d_in[0];
    const float* Wq  = (const float*)d_in[1];
    const float* bq  = (const float*)d_in[2];
    const float* Wk  = (const float*)d_in[3];
    const float* bk  = (const float*)d_in[4];
    const float* Wv  = (const float*)d_in[5];
    const float* bv  = (const float*)d_in[6];
    const float* Wo  = (const float*)d_in[7];
    const float* bo  = (const float*)d_in[8];
    const float* g1  = (const float*)d_in[9];
    const float* be1 = (const float*)d_in[10];
    const float* W1  = (const float*)d_in[11];
    const float* b1  = (const float*)d_in[12];
    const float* W2  = (const float*)d_in[13];
    const float* b2  = (const float*)d_in[14];
    const float* g2  = (const float*)d_in[15];
    const float* be2 = (const float*)d_in[16];
    float* out = (float*)d_out;

    __half *xh, *qkvh, *oh, *x1h, *hh;
    float *f32a, *x1, *bqkv;
    __half *wqkvt, *wot, *w1t, *w2t;
    cudaGetSymbolAddress((void**)&xh,    g_xh);
    cudaGetSymbolAddress((void**)&qkvh,  g_qkvh);
    cudaGetSymbolAddress((void**)&oh,    g_oh);
    cudaGetSymbolAddress((void**)&x1h,   g_x1h);
    cudaGetSymbolAddress((void**)&hh,    g_hh);
    cudaGetSymbolAddress((void**)&f32a,  g_f32a);
    cudaGetSymbolAddress((void**)&x1,    g_x1);
    cudaGetSymbolAddress((void**)&wqkvt, g_wqkvt);
    cudaGetSymbolAddress((void**)&wot,   g_wot);
    cudaGetSymbolAddress((void**)&w1t,   g_w1t);
    cudaGetSymbolAddress((void**)&w2t,   g_w2t);
    cudaGetSymbolAddress((void**)&bqkv,  g_bqkv);

    cudaFuncSetAttribute(h16_gemm_kernel,
                         cudaFuncAttributeMaxDynamicSharedMemorySize, GEMM_SMEM);

    // Convert x; transpose+convert weights; concat qkv bias
    f2h_kernel<<<(TOK * DM / 4) / 256, 256>>>(x, xh);
    {
        dim3 b(32, 8);
        transpose_h_kernel<<<dim3(DM / 32,  DM / 32),  b>>>(Wq, wqkvt,             DM,  DM);
        transpose_h_kernel<<<dim3(DM / 32,  DM / 32),  b>>>(Wk, wqkvt + 512 * DM,  DM,  DM);
        transpose_h_kernel<<<dim3(DM / 32,  DM / 32),  b>>>(Wv, wqkvt + 1024 * DM, DM,  DM);
        transpose_h_kernel<<<dim3(DM / 32,  DM / 32),  b>>>(Wo, wot, DM,  DM);
        transpose_h_kernel<<<dim3(DFF / 32, DM / 32),  b>>>(W1, w1t, DM,  DFF);
        transpose_h_kernel<<<dim3(DM / 32,  DFF / 32), b>>>(W2, w2t, DFF, DM);
        bias_concat_kernel<<<DQKV / 256, 256>>>(bq, bk, bv, bqkv);
    }

    dim3 gQKV(DQKV / 128, TOK / 128);  // (12, 512)
    dim3 gD  (DM   / 128, TOK / 128);  // (4, 512)
    dim3 gFF (DFF  / 128, TOK / 128);  // (16, 512)

    // Fused QKV projection -> qkvh [TOK, 1536] (fp16)
    h16_gemm_kernel<<<gQKV, 256, GEMM_SMEM>>>(xh, wqkvt, bqkv, nullptr,
                                              nullptr, qkvh, TOK, DQKV, DM, 0);

    // Block-local window attention
    window_attn_kernel<<<NWIN * NHEAD, 256>>>(qkvh, oh);

    // Output projection + residual(x) -> f32a = x + attn_out
    h16_gemm_kernel<<<gD, 256, GEMM_SMEM>>>(oh, wot, bo, x,
                                            f32a, nullptr, TOK, DM, DM, 0);

    // LN1 -> x1 (fp32) + x1h (fp16)
    ln_kernel<<<TOK, 128>>>(f32a, g1, be1, x1, x1h);

    // FFN
    h16_gemm_kernel<<<gFF, 256, GEMM_SMEM>>>(x1h, w1t, b1, nullptr,
                                             nullptr, hh, TOK, DFF, DM, 1);
    // W2 + residual(x1) -> f32a = x1 + ff_out
    h16_gemm_kernel<<<gD, 256, GEMM_SMEM>>>(hh, w2t, b2, x1,
                                            f32a, nullptr, TOK, DM, DFF, 0);

    // LN2 -> output (fp32)
    ln_kernel<<<TOK, 128>>>(f32a, g2, be2, out, nullptr);
}

// round 9
// speedup vs baseline: 1.0762x; 1.0380x over previous
#include <cuda_runtime.h>
#include <cuda_fp16.h>
#include <cstdint>

// Problem constants
#define TOK   65536      // B*S = 8*8192
#define DM    512
#define DQKV  1536
#define DFF   2048
#define NHEAD 8
#define DH    64
#define WIN   32
#define NWIN  2048       // TOK/WIN
#define EPSLN 1e-5f

// ---------------------------------------------------------------------------
// Scratch (device globals; allocation-free per harness rules)
// ---------------------------------------------------------------------------
__device__ __half g_xh  [(size_t)TOK * DM];
__device__ __half g_qkvh[(size_t)TOK * DQKV];
__device__ __half g_oh  [(size_t)TOK * DM];
__device__ __half g_x1h [(size_t)TOK * DM];
__device__ __half g_hh  [(size_t)TOK * DFF];
__device__ float  g_f32a[(size_t)TOK * DM];   // x+attn_out, then x1+ff_out
__device__ float  g_x1  [(size_t)TOK * DM];
// Transposed (N-major) fp16 weights
__device__ __half g_wqkvt[(size_t)DQKV * DM];
__device__ __half g_wot  [DM * DM];
__device__ __half g_w1t  [(size_t)DFF * DM];
__device__ __half g_w2t  [(size_t)DM * DFF];
__device__ float  g_bqkv [DQKV];

// ---------------------------------------------------------------------------
// fp32 -> fp16 convert
// ---------------------------------------------------------------------------
__global__ void f2h_kernel(const float* __restrict__ x, __half* __restrict__ xh)
{
    size_t i = (size_t)blockIdx.x * blockDim.x + threadIdx.x;
    float4 v = ((const float4*)x)[i];
    __half2 h0 = __floats2half2_rn(v.x, v.y);
    __half2 h1 = __floats2half2_rn(v.z, v.w);
    uint2 u;
    u.x = *(uint32_t*)&h0;
    u.y = *(uint32_t*)&h1;
    ((uint2*)xh)[i] = u;
}

__global__ void bias_concat_kernel(const float* __restrict__ bq,
                                   const float* __restrict__ bk,
                                   const float* __restrict__ bv,
                                   float* __restrict__ bqkv)
{
    int i = blockIdx.x * blockDim.x + threadIdx.x;
    const float* src = (i < DM) ? bq : (i < 2 * DM) ? bk : bv;
    bqkv[i] = src[i & (DM - 1)];
}

// ---------------------------------------------------------------------------
// Weight transpose with fp16 rounding: W[K,N] fp32 -> Wt[N,K] fp16
// ---------------------------------------------------------------------------
__global__ void transpose_h_kernel(const float* __restrict__ W,
                                   __half* __restrict__ Wt, int K, int N)
{
    __shared__ float t[32][33];
    const int n0 = blockIdx.x * 32, k0 = blockIdx.y * 32;
    const int tx = threadIdx.x, ty = threadIdx.y;
#pragma unroll
    for (int i = ty; i < 32; i += 8)
        t[i][tx] = W[(size_t)(k0 + i) * N + n0 + tx];
    __syncthreads();
#pragma unroll
    for (int i = ty; i < 32; i += 8)
        Wt[(size_t)(n0 + i) * K + k0 + tx] = __float2half_rn(t[tx][i]);
}

// ---------------------------------------------------------------------------
// FP16 tensor-core GEMM: C[M,N] = A[M,K] @ Bt[N,K]^T + bias (+residual, ReLU)
// CTA tile 128x128, BK=64 halfs, 256 threads (8 warps of 32x64 warp-tiles),
// 2-stage double-buffered cp.async (R4-proven config), ldmatrix,
// mma.sync.m16n8k16. 72KB smem, 2 CTAs/SM.
// ---------------------------------------------------------------------------
#define GBK 64
#define HSTRIDE 72                     // halfs per smem row (64 data + 8 pad)
#define ABUF_BYTES (128 * HSTRIDE * 2) // 18432 B per stage per operand
#define GEMM_SMEM (4 * ABUF_BYTES)     // 73728 B (2 stages x 2 operands)

__device__ __forceinline__ void ldsm_x4(uint32_t r[4], uint32_t addr)
{
    asm volatile("ldmatrix.sync.aligned.m8n8.x4.shared.b16 {%0,%1,%2,%3}, [%4];"
                 : "=r"(r[0]), "=r"(r[1]), "=r"(r[2]), "=r"(r[3]) : "r"(addr));
}

__device__ __forceinline__ void mma_f16(float c[4], const uint32_t a[4],
                                        const uint32_t b[2])
{
    asm volatile(
        "mma.sync.aligned.m16n8k16.row.col.f32.f16.f16.f32 "
        "{%0,%1,%2,%3}, {%4,%5,%6,%7}, {%8,%9}, {%0,%1,%2,%3};"
        : "+f"(c[0]), "+f"(c[1]), "+f"(c[2]), "+f"(c[3])
        : "r"(a[0]), "r"(a[1]), "r"(a[2]), "r"(a[3]), "r"(b[0]), "r"(b[1]));
}

__device__ __forceinline__ void cp16(uint32_t smem, const __half* gmem)
{
    asm volatile("cp.async.cg.shared.global [%0], [%1], 16;"
                 :: "r"(smem), "l"(gmem));
}

__global__ __launch_bounds__(256, 2) void h16_gemm_kernel(
    const __half* __restrict__ A, const __half* __restrict__ Bt,
    const float* __restrict__ bias, const float* __restrict__ Radd,
    float* __restrict__ Cf, __half* __restrict__ Ch,
    int M, int N, int K, int relu)
{
    extern __shared__ __half smem_dyn[];

    const int tid = threadIdx.x;
    const int bm = blockIdx.y, bn = blockIdx.x;
    const int wid = tid >> 5, lane = tid & 31;
    const int warp_m = wid & 3;          // 4 m-warps * 32 rows
    const int warp_n = wid >> 2;         // 2 n-warps * 64 cols
    const int gid = lane >> 2, ctid = lane & 3;
    const int mat = lane >> 3, rin = lane & 7;

    const uint32_t as_base = (uint32_t)__cvta_generic_to_shared(smem_dyn);
    const uint32_t bs_base = as_base + 2 * ABUF_BYTES;

    // cp.async indices: 1024 16B-chunks per tile per operand, 4 per thread
    int ldr[4], ldc[4];
#pragma unroll
    for (int i = 0; i < 4; i++) {
        int c = tid + i * 256;
        ldr[i] = c >> 3;
        ldc[i] = (c & 7) * 8;
    }

    // ldmatrix per-lane byte offsets (within a stage buffer), excluding k-step
    uint32_t a_off[2], b_off[4];
#pragma unroll
    for (int mt = 0; mt < 2; mt++)
        a_off[mt] = ((warp_m * 32 + mt * 16 + (mat & 1) * 8 + rin) * HSTRIDE
                     + (mat >> 1) * 8) * 2;
#pragma unroll
    for (int ntp = 0; ntp < 4; ntp++)
        b_off[ntp] = ((warp_n * 64 + ntp * 16 + (mat >> 1) * 8 + rin) * HSTRIDE
                      + (mat & 1) * 8) * 2;

    float acc[2][8][4];
#pragma unroll
    for (int mt = 0; mt < 2; mt++)
#pragma unroll
        for (int nt = 0; nt < 8; nt++)
#pragma unroll
            for (int i = 0; i < 4; i++) acc[mt][nt][i] = 0.0f;

    const __half* Abase = A  + (size_t)(bm * 128) * K;
    const __half* Bbase = Bt + (size_t)(bn * 128) * K;
    const int ntiles = K / GBK;

    // Prologue: tile 0 -> stage 0
    {
#pragma unroll
        for (int i = 0; i < 4; i++) {
            cp16(as_base + (ldr[i] * HSTRIDE + ldc[i]) * 2,
                 Abase + (size_t)ldr[i] * K + ldc[i]);
            cp16(bs_base + (ldr[i] * HSTRIDE + ldc[i]) * 2,
                 Bbase + (size_t)ldr[i] * K + ldc[i]);
        }
        asm volatile("cp.async.commit_group;");
    }

    for (int t = 0; t < ntiles; t++) {
        const int buf = t & 1;
        if (t + 1 < ntiles) {
            const int nb = buf ^ 1;
            const int k0 = (t + 1) * GBK;
            const __half* Ap = Abase + k0;
            const __half* Bp = Bbase + k0;
            const uint32_t ao = as_base + nb * ABUF_BYTES;
            const uint32_t bo = bs_base + nb * ABUF_BYTES;
#pragma unroll
            for (int i = 0; i < 4; i++) {
                cp16(ao + (ldr[i] * HSTRIDE + ldc[i]) * 2,
                     Ap + (size_t)ldr[i] * K + ldc[i]);
                cp16(bo + (ldr[i] * HSTRIDE + ldc[i]) * 2,
                     Bp + (size_t)ldr[i] * K + ldc[i]);
            }
            asm volatile("cp.async.commit_group;");
            asm volatile("cp.async.wait_group 1;");
        } else {
            asm volatile("cp.async.wait_group 0;");
        }
        __syncthreads();

        const uint32_t ab = as_base + buf * ABUF_BYTES;
        const uint32_t bb = bs_base + buf * ABUF_BYTES;
#pragma unroll
        for (int ks = 0; ks < 4; ks++) {
            const uint32_t kkb = ks * 32;   // 16 halfs * 2B
            uint32_t af[2][4];
#pragma unroll
            for (int mt = 0; mt < 2; mt++)
                ldsm_x4(af[mt], ab + a_off[mt] + kkb);
            uint32_t bf[8][2];
#pragma unroll
            for (int ntp = 0; ntp < 4; ntp++) {
                uint32_t qd[4];
                ldsm_x4(qd, bb + b_off[ntp] + kkb);
                bf[2 * ntp][0]     = qd[0]; bf[2 * ntp][1]     = qd[1];
                bf[2 * ntp + 1][0] = qd[2]; bf[2 * ntp + 1][1] = qd[3];
            }
#pragma unroll
            for (int mt = 0; mt < 2; mt++)
#pragma unroll
                for (int nt = 0; nt < 8; nt++)
                    mma_f16(acc[mt][nt], af[mt], bf[nt]);
        }
        __syncthreads();
    }

    // Epilogue: bias (+residual, +ReLU) -> fp32 or fp16 output
#pragma unroll
    for (int mt = 0; mt < 2; mt++) {
        const int r0 = bm * 128 + warp_m * 32 + mt * 16 + gid;
#pragma unroll
        for (int nt = 0; nt < 8; nt++) {
            const int col = bn * 128 + warp_n * 64 + nt * 8 + 2 * ctid;
            const float b0 = bias[col], b1 = bias[col + 1];
            float2 v0, v1;
            v0.x = acc[mt][nt][0] + b0; v0.y = acc[mt][nt][1] + b1;
            v1.x = acc[mt][nt][2] + b0; v1.y = acc[mt][nt][3] + b1;
            const size_t base0 = (size_t)r0 * N + col;
            const size_t base1 = (size_t)(r0 + 8) * N + col;
            if (Radd) {
                float2 ra = *(const float2*)(Radd + base0);
                float2 rb = *(const float2*)(Radd + base1);
                v0.x += ra.x; v0.y += ra.y;
                v1.x += rb.x; v1.y += rb.y;
            }
            if (relu) {
                v0.x = fmaxf(v0.x, 0.f); v0.y = fmaxf(v0.y, 0.f);
                v1.x = fmaxf(v1.x, 0.f); v1.y = fmaxf(v1.y, 0.f);
            }
            if (Cf) {
                *(float2*)(Cf + base0) = v0;
                *(float2*)(Cf + base1) = v1;
            } else {
                __half2 h0 = __floats2half2_rn(v0.x, v0.y);
                __half2 h1 = __floats2half2_rn(v1.x, v1.y);
                *(__half2*)(Ch + base0) = h0;
                *(__half2*)(Ch + base1) = h1;
            }
        }
    }
}

// ---------------------------------------------------------------------------
// Window attention (reads packed qkv [TOK, 1536], writes oh [TOK, 512])
// ---------------------------------------------------------------------------
__global__ __launch_bounds__(256) void window_attn_kernel(
    const __half* __restrict__ qkv, __half* __restrict__ o)
{
    const int bid = blockIdx.x;
    const int h = bid & (NHEAD - 1);
    const int w = bid >> 3;
    const int t0 = w * WIN;
    const int tid = threadIdx.x;

    __shared__ float qs[WIN][DH + 1];
    __shared__ float ks[WIN][DH + 1];
    __shared__ float vs[WIN][DH + 1];
    __shared__ float sc[WIN][WIN + 1];

    {
        const int row = tid >> 3;
        const int h8 = (tid & 7) * 8;
        const size_t base = (size_t)(t0 + row) * DQKV + h * DH + h8;
        uint4 uq = *(const uint4*)(qkv + base);
        uint4 uk = *(const uint4*)(qkv + base + DM);
        uint4 uv = *(const uint4*)(qkv + base + 2 * DM);
        const __half2* hq = (const __half2*)&uq;
        const __half2* hk = (const __half2*)&uk;
        const __half2* hv = (const __half2*)&uv;
#pragma unroll
        for (int j = 0; j < 4; j++) {
            float2 fq = __half22float2(hq[j]);
            float2 fk = __half22float2(hk[j]);
            float2 fv = __half22float2(hv[j]);
            qs[row][h8 + 2 * j]     = fq.x; qs[row][h8 + 2 * j + 1] = fq.y;
            ks[row][h8 + 2 * j]     = fk.x; ks[row][h8 + 2 * j + 1] = fk.y;
            vs[row][h8 + 2 * j]     = fv.x; vs[row][h8 + 2 * j + 1] = fv.y;
        }
    }
    __syncthreads();

#pragma unroll
    for (int i = 0; i < 4; i++) {
        int lin = tid + i * 256;
        int r = lin >> 5, c = lin & 31;
        float s = 0.f;
#pragma unroll
        for (int d = 0; d < DH; d++) s += qs[r][d] * ks[c][d];
        sc[r][c] = s * 0.125f;
    }
    __syncthreads();

    if (tid < WIN) {
        float m = -1e30f;
#pragma unroll
        for (int j = 0; j < WIN; j++) m = fmaxf(m, sc[tid][j]);
        float sum = 0.f;
#pragma unroll
        for (int j = 0; j < WIN; j++) {
            float e = __expf(sc[tid][j] - m);
            sc[tid][j] = e;
            sum += e;
        }
        float inv = 1.0f / sum;
#pragma unroll
        for (int j = 0; j < WIN; j++) sc[tid][j] *= inv;
    }
    __syncthreads();

#pragma unroll
    for (int i = 0; i < 4; i++) {
        int lin = tid + i * 256;
        int r = lin >> 5, d2 = (lin & 31) * 2;
        float s0 = 0.f, s1 = 0.f;
#pragma unroll
        for (int j = 0; j < WIN; j++) {
            float a = sc[r][j];
            s0 += a * vs[j][d2];
            s1 += a * vs[j][d2 + 1];
        }
        *(__half2*)(o + (size_t)(t0 + r) * DM + h * DH + d2) =
            __floats2half2_rn(s0, s1);
    }
}

// ---------------------------------------------------------------------------
// LayerNorm over a pre-summed row. One block (128 threads) per token row.
// ---------------------------------------------------------------------------
__global__ __launch_bounds__(128) void ln_kernel(
    const float* __restrict__ xr,
    const float* __restrict__ g, const float* __restrict__ b,
    float* __restrict__ y, __half* __restrict__ yh)
{
    const int row = blockIdx.x;
    const int tid = threadIdx.x;

    float4 xv = ((const float4*)(xr + (size_t)row * DM))[tid];
    float v0 = xv.x, v1 = xv.y, v2 = xv.z, v3 = xv.w;

    __shared__ float red[4];
    float s = v0 + v1 + v2 + v3;
#pragma unroll
    for (int off = 16; off > 0; off >>= 1) s += __shfl_xor_sync(0xffffffffu, s, off);
    if ((tid & 31) == 0) red[tid >> 5] = s;
    __syncthreads();
    const float mu = (red[0] + red[1] + red[2] + red[3]) * (1.0f / DM);

    float d0 = v0 - mu, d1 = v1 - mu, d2 = v2 - mu, d3 = v3 - mu;
    float qsum = d0 * d0 + d1 * d1 + d2 * d2 + d3 * d3;
    __syncthreads();
#pragma unroll
    for (int off = 16; off > 0; off >>= 1) qsum += __shfl_xor_sync(0xffffffffu, qsum, off);
    if ((tid & 31) == 0) red[tid >> 5] = qsum;
    __syncthreads();
    const float var = (red[0] + red[1] + red[2] + red[3]) * (1.0f / DM);
    const float inv = rsqrtf(var + EPSLN);

    float4 gv = ((const float4*)g)[tid];
    float4 bv = ((const float4*)b)[tid];
    float4 out;
    out.x = d0 * inv * gv.x + bv.x;
    out.y = d1 * inv * gv.y + bv.y;
    out.z = d2 * inv * gv.z + bv.z;
    out.w = d3 * inv * gv.w + bv.w;
    ((float4*)(y + (size_t)row * DM))[tid] = out;
    if (yh) {
        __half2 h0 = __floats2half2_rn(out.x, out.y);
        __half2 h1 = __floats2half2_rn(out.z, out.w);
        uint2 u;
        u.x = *(uint32_t*)&h0;
        u.y = *(uint32_t*)&h1;
        ((uint2*)(yh + (size_t)row * DM))[tid] = u;
    }
}

// ---------------------------------------------------------------------------
// Launch
// ---------------------------------------------------------------------------
extern "C" void kernel_launch(void* const* d_in, const int* in_sizes, int n_in,
                              void* d_out, int out_size)
{
    (void)in_sizes; (void)n_in; (void)out_size;
    const float* x   = (const float*)d_in[0];
    const float* Wq  = (const float*)d_in[1];
    const float* bq  = (const float*)d_in[2];
    const float* Wk  = (const float*)d_in[3];
    const float* bk  = (const float*)d_in[4];
    const float* Wv  = (const float*)d_in[5];
    const float* bv  = (const float*)d_in[6];
    const float* Wo  = (const float*)d_in[7];
    const float* bo  = (const float*)d_in[8];
    const float* g1  = (const float*)d_in[9];
    const float* be1 = (const float*)d_in[10];
    const float* W1  = (const float*)d_in[11];
    const float* b1  = (const float*)d_in[12];
    const float* W2  = (const float*)d_in[13];
    const float* b2  = (const float*)d_in[14];
    const float* g2  = (const float*)d_in[15];
    const float* be2 = (const float*)d_in[16];
    float* out = (float*)d_out;

    __half *xh, *qkvh, *oh, *x1h, *hh;
    float *f32a, *x1, *bqkv;
    __half *wqkvt, *wot, *w1t, *w2t;
    cudaGetSymbolAddress((void**)&xh,    g_xh);
    cudaGetSymbolAddress((void**)&qkvh,  g_qkvh);
    cudaGetSymbolAddress((void**)&oh,    g_oh);
    cudaGetSymbolAddress((void**)&x1h,   g_x1h);
    cudaGetSymbolAddress((void**)&hh,    g_hh);
    cudaGetSymbolAddress((void**)&f32a,  g_f32a);
    cudaGetSymbolAddress((void**)&x1,    g_x1);
    cudaGetSymbolAddress((void**)&wqkvt, g_wqkvt);
    cudaGetSymbolAddress((void**)&wot,   g_wot);
    cudaGetSymbolAddress((void**)&w1t,   g_w1t);
    cudaGetSymbolAddress((void**)&w2t,   g_w2t);
    cudaGetSymbolAddress((void**)&bqkv,  g_bqkv);

    cudaFuncSetAttribute(h16_gemm_kernel,
                         cudaFuncAttributeMaxDynamicSharedMemorySize, GEMM_SMEM);

    // Convert x; transpose+convert weights; concat qkv bias
    f2h_kernel<<<(TOK * DM / 4) / 256, 256>>>(x, xh);
    {
        dim3 b(32, 8);
        transpose_h_kernel<<<dim3(DM / 32,  DM / 32),  b>>>(Wq, wqkvt,             DM,  DM);
        transpose_h_kernel<<<dim3(DM / 32,  DM / 32),  b>>>(Wk, wqkvt + 512 * DM,  DM,  DM);
        transpose_h_kernel<<<dim3(DM / 32,  DM / 32),  b>>>(Wv, wqkvt + 1024 * DM, DM,  DM);
        transpose_h_kernel<<<dim3(DM / 32,  DM / 32),  b>>>(Wo, wot, DM,  DM);
        transpose_h_kernel<<<dim3(DFF / 32, DM / 32),  b>>>(W1, w1t, DM,  DFF);
        transpose_h_kernel<<<dim3(DM / 32,  DFF / 32), b>>>(W2, w2t, DFF, DM);
        bias_concat_kernel<<<DQKV / 256, 256>>>(bq, bk, bv, bqkv);
    }

    dim3 gQKV(DQKV / 128, TOK / 128);  // (12, 512)
    dim3 gD  (DM   / 128, TOK / 128);  // (4, 512)
    dim3 gFF (DFF  / 128, TOK / 128);  // (16, 512)

    // Fused QKV projection -> qkvh [TOK, 1536] (fp16)
    h16_gemm_kernel<<<gQKV, 256, GEMM_SMEM>>>(xh, wqkvt, bqkv, nullptr,
                                              nullptr, qkvh, TOK, DQKV, DM, 0);

    // Block-local window attention
    window_attn_kernel<<<NWIN * NHEAD, 256>>>(qkvh, oh);

    // Output projection + residual(x) -> f32a = x + attn_out
    h16_gemm_kernel<<<gD, 256, GEMM_SMEM>>>(oh, wot, bo, x,
                                            f32a, nullptr, TOK, DM, DM, 0);

    // LN1 -> x1 (fp32) + x1h (fp16)
    ln_kernel<<<TOK, 128>>>(f32a, g1, be1, x1, x1h);

    // FFN
    h16_gemm_kernel<<<gFF, 256, GEMM_SMEM>>>(x1h, w1t, b1, nullptr,
                                             nullptr, hh, TOK, DFF, DM, 1);
    // W2 + residual(x1) -> f32a = x1 + ff_out
    h16_gemm_kernel<<<gD, 256, GEMM_SMEM>>>(hh, w2t, b2, x1,
                                            f32a, nullptr, TOK, DM, DFF, 0);

    // LN2 -> output (fp32)
    ln_kernel<<<TOK, 128>>>(f32a, g2, be2, out, nullptr);
}

// round 10
// speedup vs baseline: 1.0940x; 1.0165x over previous
#include <cuda_runtime.h>
#include <cuda_fp16.h>
#include <cstdint>

// Problem constants
#define TOK   65536      // B*S = 8*8192
#define DM    512
#define DQKV  1536
#define DFF   2048
#define NHEAD 8
#define DH    64
#define WIN   32
#define NWIN  2048       // TOK/WIN
#define EPSLN 1e-5f

// ---------------------------------------------------------------------------
// Scratch (device globals; allocation-free per harness rules)
// ---------------------------------------------------------------------------
__device__ __half g_xh  [(size_t)TOK * DM];
__device__ __half g_qkvh[(size_t)TOK * DQKV];
__device__ __half g_oh  [(size_t)TOK * DM];
__device__ __half g_x1h [(size_t)TOK * DM];
__device__ __half g_hh  [(size_t)TOK * DFF];
__device__ float  g_f32a[(size_t)TOK * DM];   // x+attn_out, then x1+ff_out
// Transposed (N-major) fp16 weights
__device__ __half g_wqkvt[(size_t)DQKV * DM];
__device__ __half g_wot  [DM * DM];
__device__ __half g_w1t  [(size_t)DFF * DM];
__device__ __half g_w2t  [(size_t)DM * DFF];
__device__ float  g_bqkv [DQKV];

// ---------------------------------------------------------------------------
// fp32 -> fp16 convert (x)
// ---------------------------------------------------------------------------
__global__ void f2h_kernel(const float* __restrict__ x, __half* __restrict__ xh)
{
    size_t i = (size_t)blockIdx.x * blockDim.x + threadIdx.x;
    float4 v = ((const float4*)x)[i];
    __half2 h0 = __floats2half2_rn(v.x, v.y);
    __half2 h1 = __floats2half2_rn(v.z, v.w);
    uint2 u;
    u.x = *(uint32_t*)&h0;
    u.y = *(uint32_t*)&h1;
    ((uint2*)xh)[i] = u;
}

// ---------------------------------------------------------------------------
// Fused prep: all 6 weight transposes (fp32->fp16) + qkv bias concat.
// Flat grid of 3073 tiles; block (32,8).
//   [0,1024)    : Wq/Wk/Wv/Wo  (256 32x32 tiles each, N=K=512)
//   [1024,2048) : W1 (N=2048, K=512; 64x16 tiles)
//   [2048,3072) : W2 (N=512, K=2048; 16x64 tiles)
//   3072        : bias concat
// ---------------------------------------------------------------------------
__global__ void prep_kernel(
    const float* __restrict__ Wq, const float* __restrict__ Wk,
    const float* __restrict__ Wv, const float* __restrict__ Wo,
    const float* __restrict__ W1, const float* __restrict__ W2,
    __half* __restrict__ wqkvt, __half* __restrict__ wot,
    __half* __restrict__ w1t, __half* __restrict__ w2t,
    const float* __restrict__ bq, const float* __restrict__ bk,
    const float* __restrict__ bv, float* __restrict__ bqkv)
{
    const int t = blockIdx.x;
    const int tx = threadIdx.x, ty = threadIdx.y;

    if (t >= 3072) {   // bias concat
        const int tid = ty * 32 + tx;
        for (int i = tid; i < DQKV; i += 256) {
            const float* src = (i < DM) ? bq : (i < 2 * DM) ? bk : bv;
            bqkv[i] = src[i & (DM - 1)];
        }
        return;
    }

    const float* W;
    __half* Wt;
    int K, N, idx;
    if (t < 1024) {
        const int m = t >> 8;   // 0..3 -> Wq,Wk,Wv,Wo
        idx = t & 255;
        K = DM; N = DM;
        W  = (m == 0) ? Wq : (m == 1) ? Wk : (m == 2) ? Wv : Wo;
        Wt = (m == 0) ? wqkvt
           : (m == 1) ? (wqkvt + 512 * DM)
           : (m == 2) ? (wqkvt + 1024 * DM) : wot;
    } else if (t < 2048) {
        idx = t - 1024; W = W1; Wt = w1t; K = DM; N = DFF;
    } else {
        idx = t - 2048; W = W2; Wt = w2t; K = DFF; N = DM;
    }
    const int ntx = N / 32;
    const int n0 = (idx % ntx) * 32, k0 = (idx / ntx) * 32;

    __shared__ float tb[32][33];
#pragma unroll
    for (int i = ty; i < 32; i += 8)
        tb[i][tx] = W[(size_t)(k0 + i) * N + n0 + tx];
    __syncthreads();
#pragma unroll
    for (int i = ty; i < 32; i += 8)
        Wt[(size_t)(n0 + i) * K + k0 + tx] = __float2half_rn(tb[tx][i]);
}

// ---------------------------------------------------------------------------
// FP16 tensor-core GEMM: C[M,N] = A[M,K] @ Bt[N,K]^T + bias
//   (+fp32 residual Radd or fp16 residual RaddH, opt ReLU)
// CTA tile 128x128, BK=64 halfs, 256 threads (8 warps of 32x64 warp-tiles),
// 2-stage double-buffered cp.async (proven config), ldmatrix,
// mma.sync.m16n8k16. 72KB smem, 2 CTAs/SM.
// ---------------------------------------------------------------------------
#define GBK 64
#define HSTRIDE 72                     // halfs per smem row (64 data + 8 pad)
#define ABUF_BYTES (128 * HSTRIDE * 2) // 18432 B per stage per operand
#define GEMM_SMEM (4 * ABUF_BYTES)     // 73728 B (2 stages x 2 operands)

__device__ __forceinline__ void ldsm_x4(uint32_t r[4], uint32_t addr)
{
    asm volatile("ldmatrix.sync.aligned.m8n8.x4.shared.b16 {%0,%1,%2,%3}, [%4];"
                 : "=r"(r[0]), "=r"(r[1]), "=r"(r[2]), "=r"(r[3]) : "r"(addr));
}

__device__ __forceinline__ void mma_f16(float c[4], const uint32_t a[4],
                                        const uint32_t b[2])
{
    asm volatile(
        "mma.sync.aligned.m16n8k16.row.col.f32.f16.f16.f32 "
        "{%0,%1,%2,%3}, {%4,%5,%6,%7}, {%8,%9}, {%0,%1,%2,%3};"
        : "+f"(c[0]), "+f"(c[1]), "+f"(c[2]), "+f"(c[3])
        : "r"(a[0]), "r"(a[1]), "r"(a[2]), "r"(a[3]), "r"(b[0]), "r"(b[1]));
}

__device__ __forceinline__ void cp16(uint32_t smem, const __half* gmem)
{
    asm volatile("cp.async.cg.shared.global [%0], [%1], 16;"
                 :: "r"(smem), "l"(gmem));
}

__global__ __launch_bounds__(256, 2) void h16_gemm_kernel(
    const __half* __restrict__ A, const __half* __restrict__ Bt,
    const float* __restrict__ bias,
    const float* __restrict__ Radd, const __half* __restrict__ RaddH,
    float* __restrict__ Cf, __half* __restrict__ Ch,
    int M, int N, int K, int relu)
{
    extern __shared__ __half smem_dyn[];

    const int tid = threadIdx.x;
    const int bm = blockIdx.y, bn = blockIdx.x;
    const int wid = tid >> 5, lane = tid & 31;
    const int warp_m = wid & 3;          // 4 m-warps * 32 rows
    const int warp_n = wid >> 2;         // 2 n-warps * 64 cols
    const int gid = lane >> 2, ctid = lane & 3;
    const int mat = lane >> 3, rin = lane & 7;

    const uint32_t as_base = (uint32_t)__cvta_generic_to_shared(smem_dyn);
    const uint32_t bs_base = as_base + 2 * ABUF_BYTES;

    // cp.async indices: 1024 16B-chunks per tile per operand, 4 per thread
    int ldr[4], ldc[4];
#pragma unroll
    for (int i = 0; i < 4; i++) {
        int c = tid + i * 256;
        ldr[i] = c >> 3;
        ldc[i] = (c & 7) * 8;
    }

    // ldmatrix per-lane byte offsets (within a stage buffer), excluding k-step
    uint32_t a_off[2], b_off[4];
#pragma unroll
    for (int mt = 0; mt < 2; mt++)
        a_off[mt] = ((warp_m * 32 + mt * 16 + (mat & 1) * 8 + rin) * HSTRIDE
                     + (mat >> 1) * 8) * 2;
#pragma unroll
    for (int ntp = 0; ntp < 4; ntp++)
        b_off[ntp] = ((warp_n * 64 + ntp * 16 + (mat >> 1) * 8 + rin) * HSTRIDE
                      + (mat & 1) * 8) * 2;

    float acc[2][8][4];
#pragma unroll
    for (int mt = 0; mt < 2; mt++)
#pragma unroll
        for (int nt = 0; nt < 8; nt++)
#pragma unroll
            for (int i = 0; i < 4; i++) acc[mt][nt][i] = 0.0f;

    const __half* Abase = A  + (size_t)(bm * 128) * K;
    const __half* Bbase = Bt + (size_t)(bn * 128) * K;
    const int ntiles = K / GBK;

    // Prologue: tile 0 -> stage 0
    {
#pragma unroll
        for (int i = 0; i < 4; i++) {
            cp16(as_base + (ldr[i] * HSTRIDE + ldc[i]) * 2,
                 Abase + (size_t)ldr[i] * K + ldc[i]);
            cp16(bs_base + (ldr[i] * HSTRIDE + ldc[i]) * 2,
                 Bbase + (size_t)ldr[i] * K + ldc[i]);
        }
        asm volatile("cp.async.commit_group;");
    }

    for (int t = 0; t < ntiles; t++) {
        const int buf = t & 1;
        if (t + 1 < ntiles) {
            const int nb = buf ^ 1;
            const int k0 = (t + 1) * GBK;
            const __half* Ap = Abase + k0;
            const __half* Bp = Bbase + k0;
            const uint32_t ao = as_base + nb * ABUF_BYTES;
            const uint32_t bo = bs_base + nb * ABUF_BYTES;
#pragma unroll
            for (int i = 0; i < 4; i++) {
                cp16(ao + (ldr[i] * HSTRIDE + ldc[i]) * 2,
                     Ap + (size_t)ldr[i] * K + ldc[i]);
                cp16(bo + (ldr[i] * HSTRIDE + ldc[i]) * 2,
                     Bp + (size_t)ldr[i] * K + ldc[i]);
            }
            asm volatile("cp.async.commit_group;");
            asm volatile("cp.async.wait_group 1;");
        } else {
            asm volatile("cp.async.wait_group 0;");
        }
        __syncthreads();

        const uint32_t ab = as_base + buf * ABUF_BYTES;
        const uint32_t bb = bs_base + buf * ABUF_BYTES;
#pragma unroll
        for (int ks = 0; ks < 4; ks++) {
            const uint32_t kkb = ks * 32;   // 16 halfs * 2B
            uint32_t af[2][4];
#pragma unroll
            for (int mt = 0; mt < 2; mt++)
                ldsm_x4(af[mt], ab + a_off[mt] + kkb);
            uint32_t bf[8][2];
#pragma unroll
            for (int ntp = 0; ntp < 4; ntp++) {
                uint32_t qd[4];
                ldsm_x4(qd, bb + b_off[ntp] + kkb);
                bf[2 * ntp][0]     = qd[0]; bf[2 * ntp][1]     = qd[1];
                bf[2 * ntp + 1][0] = qd[2]; bf[2 * ntp + 1][1] = qd[3];
            }
#pragma unroll
            for (int mt = 0; mt < 2; mt++)
#pragma unroll
                for (int nt = 0; nt < 8; nt++)
                    mma_f16(acc[mt][nt], af[mt], bf[nt]);
        }
        __syncthreads();
    }

    // Epilogue: bias (+residual fp32/fp16, +ReLU) -> fp32 or fp16 output
#pragma unroll
    for (int mt = 0; mt < 2; mt++) {
        const int r0 = bm * 128 + warp_m * 32 + mt * 16 + gid;
#pragma unroll
        for (int nt = 0; nt < 8; nt++) {
            const int col = bn * 128 + warp_n * 64 + nt * 8 + 2 * ctid;
            const float b0 = bias[col], b1 = bias[col + 1];
            float2 v0, v1;
            v0.x = acc[mt][nt][0] + b0; v0.y = acc[mt][nt][1] + b1;
            v1.x = acc[mt][nt][2] + b0; v1.y = acc[mt][nt][3] + b1;
            const size_t base0 = (size_t)r0 * N + col;
            const size_t base1 = (size_t)(r0 + 8) * N + col;
            if (Radd) {
                float2 ra = *(const float2*)(Radd + base0);
                float2 rb = *(const float2*)(Radd + base1);
                v0.x += ra.x; v0.y += ra.y;
                v1.x += rb.x; v1.y += rb.y;
            }
            if (RaddH) {
                float2 ra = __half22float2(*(const __half2*)(RaddH + base0));
                float2 rb = __half22float2(*(const __half2*)(RaddH + base1));
                v0.x += ra.x; v0.y += ra.y;
                v1.x += rb.x; v1.y += rb.y;
            }
            if (relu) {
                v0.x = fmaxf(v0.x, 0.f); v0.y = fmaxf(v0.y, 0.f);
                v1.x = fmaxf(v1.x, 0.f); v1.y = fmaxf(v1.y, 0.f);
            }
            if (Cf) {
                *(float2*)(Cf + base0) = v0;
                *(float2*)(Cf + base1) = v1;
            } else {
                __half2 h0 = __floats2half2_rn(v0.x, v0.y);
                __half2 h1 = __floats2half2_rn(v1.x, v1.y);
                *(__half2*)(Ch + base0) = h0;
                *(__half2*)(Ch + base1) = h1;
            }
        }
    }
}

// ---------------------------------------------------------------------------
// Window attention (reads packed qkv [TOK, 1536], writes oh [TOK, 512])
// ---------------------------------------------------------------------------
__global__ __launch_bounds__(256) void window_attn_kernel(
    const __half* __restrict__ qkv, __half* __restrict__ o)
{
    const int bid = blockIdx.x;
    const int h = bid & (NHEAD - 1);
    const int w = bid >> 3;
    const int t0 = w * WIN;
    const int tid = threadIdx.x;

    __shared__ float qs[WIN][DH + 1];
    __shared__ float ks[WIN][DH + 1];
    __shared__ float vs[WIN][DH + 1];
    __shared__ float sc[WIN][WIN + 1];

    {
        const int row = tid >> 3;
        const int h8 = (tid & 7) * 8;
        const size_t base = (size_t)(t0 + row) * DQKV + h * DH + h8;
        uint4 uq = *(const uint4*)(qkv + base);
        uint4 uk = *(const uint4*)(qkv + base + DM);
        uint4 uv = *(const uint4*)(qkv + base + 2 * DM);
        const __half2* hq = (const __half2*)&uq;
        const __half2* hk = (const __half2*)&uk;
        const __half2* hv = (const __half2*)&uv;
#pragma unroll
        for (int j = 0; j < 4; j++) {
            float2 fq = __half22float2(hq[j]);
            float2 fk = __half22float2(hk[j]);
            float2 fv = __half22float2(hv[j]);
            qs[row][h8 + 2 * j]     = fq.x; qs[row][h8 + 2 * j + 1] = fq.y;
            ks[row][h8 + 2 * j]     = fk.x; ks[row][h8 + 2 * j + 1] = fk.y;
            vs[row][h8 + 2 * j]     = fv.x; vs[row][h8 + 2 * j + 1] = fv.y;
        }
    }
    __syncthreads();

#pragma unroll
    for (int i = 0; i < 4; i++) {
        int lin = tid + i * 256;
        int r = lin >> 5, c = lin & 31;
        float s = 0.f;
#pragma unroll
        for (int d = 0; d < DH; d++) s += qs[r][d] * ks[c][d];
        sc[r][c] = s * 0.125f;
    }
    __syncthreads();

    if (tid < WIN) {
        float m = -1e30f;
#pragma unroll
        for (int j = 0; j < WIN; j++) m = fmaxf(m, sc[tid][j]);
        float sum = 0.f;
#pragma unroll
        for (int j = 0; j < WIN; j++) {
            float e = __expf(sc[tid][j] - m);
            sc[tid][j] = e;
            sum += e;
        }
        float inv = 1.0f / sum;
#pragma unroll
        for (int j = 0; j < WIN; j++) sc[tid][j] *= inv;
    }
    __syncthreads();

#pragma unroll
    for (int i = 0; i < 4; i++) {
        int lin = tid + i * 256;
        int r = lin >> 5, d2 = (lin & 31) * 2;
        float s0 = 0.f, s1 = 0.f;
#pragma unroll
        for (int j = 0; j < WIN; j++) {
            float a = sc[r][j];
            s0 += a * vs[j][d2];
            s1 += a * vs[j][d2 + 1];
        }
        *(__half2*)(o + (size_t)(t0 + r) * DM + h * DH + d2) =
            __floats2half2_rn(s0, s1);
    }
}

// ---------------------------------------------------------------------------
// LayerNorm over a pre-summed row. One block (128 threads) per token row.
// Optional fp32 output y and/or fp16 output yh.
// ---------------------------------------------------------------------------
__global__ __launch_bounds__(128) void ln_kernel(
    const float* __restrict__ xr,
    const float* __restrict__ g, const float* __restrict__ b,
    float* __restrict__ y, __half* __restrict__ yh)
{
    const int row = blockIdx.x;
    const int tid = threadIdx.x;

    float4 xv = ((const float4*)(xr + (size_t)row * DM))[tid];
    float v0 = xv.x, v1 = xv.y, v2 = xv.z, v3 = xv.w;

    __shared__ float red[4];
    float s = v0 + v1 + v2 + v3;
#pragma unroll
    for (int off = 16; off > 0; off >>= 1) s += __shfl_xor_sync(0xffffffffu, s, off);
    if ((tid & 31) == 0) red[tid >> 5] = s;
    __syncthreads();
    const float mu = (red[0] + red[1] + red[2] + red[3]) * (1.0f / DM);

    float d0 = v0 - mu, d1 = v1 - mu, d2 = v2 - mu, d3 = v3 - mu;
    float qsum = d0 * d0 + d1 * d1 + d2 * d2 + d3 * d3;
    __syncthreads();
#pragma unroll
    for (int off = 16; off > 0; off >>= 1) qsum += __shfl_xor_sync(0xffffffffu, qsum, off);
    if ((tid & 31) == 0) red[tid >> 5] = qsum;
    __syncthreads();
    const float var = (red[0] + red[1] + red[2] + red[3]) * (1.0f / DM);
    const float inv = rsqrtf(var + EPSLN);

    float4 gv = ((const float4*)g)[tid];
    float4 bv = ((const float4*)b)[tid];
    float4 out;
    out.x = d0 * inv * gv.x + bv.x;
    out.y = d1 * inv * gv.y + bv.y;
    out.z = d2 * inv * gv.z + bv.z;
    out.w = d3 * inv * gv.w + bv.w;
    if (y)
        ((float4*)(y + (size_t)row * DM))[tid] = out;
    if (yh) {
        __half2 h0 = __floats2half2_rn(out.x, out.y);
        __half2 h1 = __floats2half2_rn(out.z, out.w);
        uint2 u;
        u.x = *(uint32_t*)&h0;
        u.y = *(uint32_t*)&h1;
        ((uint2*)(yh + (size_t)row * DM))[tid] = u;
    }
}

// ---------------------------------------------------------------------------
// Launch
// ---------------------------------------------------------------------------
extern "C" void kernel_launch(void* const* d_in, const int* in_sizes, int n_in,
                              void* d_out, int out_size)
{
    (void)in_sizes; (void)n_in; (void)out_size;
    const float* x   = (const float*)d_in[0];
    const float* Wq  = (const float*)d_in[1];
    const float* bq  = (const float*)d_in[2];
    const float* Wk  = (const float*)d_in[3];
    const float* bk  = (const float*)d_in[4];
    const float* Wv  = (const float*)d_in[5];
    const float* bv  = (const float*)d_in[6];
    const float* Wo  = (const float*)d_in[7];
    const float* bo  = (const float*)d_in[8];
    const float* g1  = (const float*)d_in[9];
    const float* be1 = (const float*)d_in[10];
    const float* W1  = (const float*)d_in[11];
    const float* b1  = (const float*)d_in[12];
    const float* W2  = (const float*)d_in[13];
    const float* b2  = (const float*)d_in[14];
    const float* g2  = (const float*)d_in[15];
    const float* be2 = (const float*)d_in[16];
    float* out = (float*)d_out;

    __half *xh, *qkvh, *oh, *x1h, *hh;
    float *f32a, *bqkv;
    __half *wqkvt, *wot, *w1t, *w2t;
    cudaGetSymbolAddress((void**)&xh,    g_xh);
    cudaGetSymbolAddress((void**)&qkvh,  g_qkvh);
    cudaGetSymbolAddress((void**)&oh,    g_oh);
    cudaGetSymbolAddress((void**)&x1h,   g_x1h);
    cudaGetSymbolAddress((void**)&hh,    g_hh);
    cudaGetSymbolAddress((void**)&f32a,  g_f32a);
    cudaGetSymbolAddress((void**)&wqkvt, g_wqkvt);
    cudaGetSymbolAddress((void**)&wot,   g_wot);
    cudaGetSymbolAddress((void**)&w1t,   g_w1t);
    cudaGetSymbolAddress((void**)&w2t,   g_w2t);
    cudaGetSymbolAddress((void**)&bqkv,  g_bqkv);

    cudaFuncSetAttribute(h16_gemm_kernel,
                         cudaFuncAttributeMaxDynamicSharedMemorySize, GEMM_SMEM);

    // Prep: x fp16 convert + all weight transposes + bias concat (2 launches)
    f2h_kernel<<<(TOK * DM / 4) / 256, 256>>>(x, xh);
    prep_kernel<<<3073, dim3(32, 8)>>>(Wq, Wk, Wv, Wo, W1, W2,
                                       wqkvt, wot, w1t, w2t,
                                       bq, bk, bv, bqkv);

    dim3 gQKV(DQKV / 128, TOK / 128);  // (12, 512)
    dim3 gD  (DM   / 128, TOK / 128);  // (4, 512)
    dim3 gFF (DFF  / 128, TOK / 128);  // (16, 512)

    // Fused QKV projection -> qkvh [TOK, 1536] (fp16)
    h16_gemm_kernel<<<gQKV, 256, GEMM_SMEM>>>(xh, wqkvt, bqkv, nullptr, nullptr,
                                              nullptr, qkvh, TOK, DQKV, DM, 0);

    // Block-local window attention
    window_attn_kernel<<<NWIN * NHEAD, 256>>>(qkvh, oh);

    // Output projection + residual(x, fp32) -> f32a = x + attn_out
    h16_gemm_kernel<<<gD, 256, GEMM_SMEM>>>(oh, wot, bo, x, nullptr,
                                            f32a, nullptr, TOK, DM, DM, 0);

    // LN1 -> x1h (fp16 only; fp32 copy eliminated)
    ln_kernel<<<TOK, 128>>>(f32a, g1, be1, nullptr, x1h);

    // FFN
    h16_gemm_kernel<<<gFF, 256, GEMM_SMEM>>>(x1h, w1t, b1, nullptr, nullptr,
                                             nullptr, hh, TOK, DFF, DM, 1);
    // W2 + residual(x1h, fp16) -> f32a = x1 + ff_out
    h16_gemm_kernel<<<gD, 256, GEMM_SMEM>>>(hh, w2t, b2, nullptr, x1h,
                                            f32a, nullptr, TOK, DM, DFF, 0);

    // LN2 -> output (fp32)
    ln_kernel<<<TOK, 128>>>(f32a, g2, be2, out, nullptr);
}

// round 11
// speedup vs baseline: 1.1304x; 1.0333x over previous
#include <cuda_runtime.h>
#include <cuda_fp16.h>
#include <cstdint>

// Problem constants
#define TOK   65536      // B*S = 8*8192
#define DM    512
#define DQKV  1536
#define DFF   2048
#define NHEAD 8
#define DH    64
#define WIN   32
#define NWIN  2048       // TOK/WIN
#define EPSLN 1e-5f

// ---------------------------------------------------------------------------
// Scratch (device globals; allocation-free per harness rules)
// ---------------------------------------------------------------------------
__device__ __half g_xh  [(size_t)TOK * DM];
__device__ __half g_qkvh[(size_t)TOK * DQKV];
__device__ __half g_oh  [(size_t)TOK * DM];
__device__ __half g_x1h [(size_t)TOK * DM];
__device__ __half g_hh  [(size_t)TOK * DFF];
__device__ float  g_f32a[(size_t)TOK * DM];   // x+attn_out, then x1+ff_out
// Transposed (N-major) fp16 weights
__device__ __half g_wqkvt[(size_t)DQKV * DM];
__device__ __half g_wot  [DM * DM];
__device__ __half g_w1t  [(size_t)DFF * DM];
__device__ __half g_w2t  [(size_t)DM * DFF];
__device__ float  g_bqkv [DQKV];

// ---------------------------------------------------------------------------
// fp32 -> fp16 convert (x)
// ---------------------------------------------------------------------------
__global__ void f2h_kernel(const float* __restrict__ x, __half* __restrict__ xh)
{
    size_t i = (size_t)blockIdx.x * blockDim.x + threadIdx.x;
    float4 v = ((const float4*)x)[i];
    __half2 h0 = __floats2half2_rn(v.x, v.y);
    __half2 h1 = __floats2half2_rn(v.z, v.w);
    uint2 u;
    u.x = *(uint32_t*)&h0;
    u.y = *(uint32_t*)&h1;
    ((uint2*)xh)[i] = u;
}

// ---------------------------------------------------------------------------
// Fused prep: all 6 weight transposes (fp32->fp16) + qkv bias concat.
// Flat grid of 3073 tiles; block (32,8).
// ---------------------------------------------------------------------------
__global__ void prep_kernel(
    const float* __restrict__ Wq, const float* __restrict__ Wk,
    const float* __restrict__ Wv, const float* __restrict__ Wo,
    const float* __restrict__ W1, const float* __restrict__ W2,
    __half* __restrict__ wqkvt, __half* __restrict__ wot,
    __half* __restrict__ w1t, __half* __restrict__ w2t,
    const float* __restrict__ bq, const float* __restrict__ bk,
    const float* __restrict__ bv, float* __restrict__ bqkv)
{
    const int t = blockIdx.x;
    const int tx = threadIdx.x, ty = threadIdx.y;

    if (t >= 3072) {   // bias concat
        const int tid = ty * 32 + tx;
        for (int i = tid; i < DQKV; i += 256) {
            const float* src = (i < DM) ? bq : (i < 2 * DM) ? bk : bv;
            bqkv[i] = src[i & (DM - 1)];
        }
        return;
    }

    const float* W;
    __half* Wt;
    int K, N, idx;
    if (t < 1024) {
        const int m = t >> 8;   // 0..3 -> Wq,Wk,Wv,Wo
        idx = t & 255;
        K = DM; N = DM;
        W  = (m == 0) ? Wq : (m == 1) ? Wk : (m == 2) ? Wv : Wo;
        Wt = (m == 0) ? wqkvt
           : (m == 1) ? (wqkvt + 512 * DM)
           : (m == 2) ? (wqkvt + 1024 * DM) : wot;
    } else if (t < 2048) {
        idx = t - 1024; W = W1; Wt = w1t; K = DM; N = DFF;
    } else {
        idx = t - 2048; W = W2; Wt = w2t; K = DFF; N = DM;
    }
    const int ntx = N / 32;
    const int n0 = (idx % ntx) * 32, k0 = (idx / ntx) * 32;

    __shared__ float tb[32][33];
#pragma unroll
    for (int i = ty; i < 32; i += 8)
        tb[i][tx] = W[(size_t)(k0 + i) * N + n0 + tx];
    __syncthreads();
#pragma unroll
    for (int i = ty; i < 32; i += 8)
        Wt[(size_t)(n0 + i) * K + k0 + tx] = __float2half_rn(tb[tx][i]);
}

// ---------------------------------------------------------------------------
// FP16 tensor-core GEMM: C[M,N] = A[M,K] @ Bt[N,K]^T + bias
//   (+fp32 residual Radd or fp16 residual RaddH, opt ReLU)
// CTA tile 128x128, BK=64 halfs, 256 threads (8 warps of 32x64 warp-tiles),
// 2-stage double-buffered cp.async (proven config), ldmatrix,
// mma.sync.m16n8k16. 72KB smem, 2 CTAs/SM.
// ---------------------------------------------------------------------------
#define GBK 64
#define HSTRIDE 72                     // halfs per smem row (64 data + 8 pad)
#define ABUF_BYTES (128 * HSTRIDE * 2) // 18432 B per stage per operand
#define GEMM_SMEM (4 * ABUF_BYTES)     // 73728 B (2 stages x 2 operands)

__device__ __forceinline__ void ldsm_x4(uint32_t r[4], uint32_t addr)
{
    asm volatile("ldmatrix.sync.aligned.m8n8.x4.shared.b16 {%0,%1,%2,%3}, [%4];"
                 : "=r"(r[0]), "=r"(r[1]), "=r"(r[2]), "=r"(r[3]) : "r"(addr));
}

__device__ __forceinline__ void mma_f16(float c[4], const uint32_t a[4],
                                        const uint32_t b[2])
{
    asm volatile(
        "mma.sync.aligned.m16n8k16.row.col.f32.f16.f16.f32 "
        "{%0,%1,%2,%3}, {%4,%5,%6,%7}, {%8,%9}, {%0,%1,%2,%3};"
        : "+f"(c[0]), "+f"(c[1]), "+f"(c[2]), "+f"(c[3])
        : "r"(a[0]), "r"(a[1]), "r"(a[2]), "r"(a[3]), "r"(b[0]), "r"(b[1]));
}

__device__ __forceinline__ void cp16(uint32_t smem, const __half* gmem)
{
    asm volatile("cp.async.cg.shared.global [%0], [%1], 16;"
                 :: "r"(smem), "l"(gmem));
}

__global__ __launch_bounds__(256, 2) void h16_gemm_kernel(
    const __half* __restrict__ A, const __half* __restrict__ Bt,
    const float* __restrict__ bias,
    const float* __restrict__ Radd, const __half* __restrict__ RaddH,
    float* __restrict__ Cf, __half* __restrict__ Ch,
    int M, int N, int K, int relu)
{
    extern __shared__ __half smem_dyn[];

    const int tid = threadIdx.x;
    const int bm = blockIdx.y, bn = blockIdx.x;
    const int wid = tid >> 5, lane = tid & 31;
    const int warp_m = wid & 3;          // 4 m-warps * 32 rows
    const int warp_n = wid >> 2;         // 2 n-warps * 64 cols
    const int gid = lane >> 2, ctid = lane & 3;
    const int mat = lane >> 3, rin = lane & 7;

    const uint32_t as_base = (uint32_t)__cvta_generic_to_shared(smem_dyn);
    const uint32_t bs_base = as_base + 2 * ABUF_BYTES;

    // cp.async indices: 1024 16B-chunks per tile per operand, 4 per thread
    int ldr[4], ldc[4];
#pragma unroll
    for (int i = 0; i < 4; i++) {
        int c = tid + i * 256;
        ldr[i] = c >> 3;
        ldc[i] = (c & 7) * 8;
    }

    // ldmatrix per-lane byte offsets (within a stage buffer), excluding k-step
    uint32_t a_off[2], b_off[4];
#pragma unroll
    for (int mt = 0; mt < 2; mt++)
        a_off[mt] = ((warp_m * 32 + mt * 16 + (mat & 1) * 8 + rin) * HSTRIDE
                     + (mat >> 1) * 8) * 2;
#pragma unroll
    for (int ntp = 0; ntp < 4; ntp++)
        b_off[ntp] = ((warp_n * 64 + ntp * 16 + (mat >> 1) * 8 + rin) * HSTRIDE
                      + (mat & 1) * 8) * 2;

    float acc[2][8][4];
#pragma unroll
    for (int mt = 0; mt < 2; mt++)
#pragma unroll
        for (int nt = 0; nt < 8; nt++)
#pragma unroll
            for (int i = 0; i < 4; i++) acc[mt][nt][i] = 0.0f;

    const __half* Abase = A  + (size_t)(bm * 128) * K;
    const __half* Bbase = Bt + (size_t)(bn * 128) * K;
    const int ntiles = K / GBK;

    // Prologue: tile 0 -> stage 0
    {
#pragma unroll
        for (int i = 0; i < 4; i++) {
            cp16(as_base + (ldr[i] * HSTRIDE + ldc[i]) * 2,
                 Abase + (size_t)ldr[i] * K + ldc[i]);
            cp16(bs_base + (ldr[i] * HSTRIDE + ldc[i]) * 2,
                 Bbase + (size_t)ldr[i] * K + ldc[i]);
        }
        asm volatile("cp.async.commit_group;");
    }

    for (int t = 0; t < ntiles; t++) {
        const int buf = t & 1;
        if (t + 1 < ntiles) {
            const int nb = buf ^ 1;
            const int k0 = (t + 1) * GBK;
            const __half* Ap = Abase + k0;
            const __half* Bp = Bbase + k0;
            const uint32_t ao = as_base + nb * ABUF_BYTES;
            const uint32_t bo = bs_base + nb * ABUF_BYTES;
#pragma unroll
            for (int i = 0; i < 4; i++) {
                cp16(ao + (ldr[i] * HSTRIDE + ldc[i]) * 2,
                     Ap + (size_t)ldr[i] * K + ldc[i]);
                cp16(bo + (ldr[i] * HSTRIDE + ldc[i]) * 2,
                     Bp + (size_t)ldr[i] * K + ldc[i]);
            }
            asm volatile("cp.async.commit_group;");
            asm volatile("cp.async.wait_group 1;");
        } else {
            asm volatile("cp.async.wait_group 0;");
        }
        __syncthreads();

        const uint32_t ab = as_base + buf * ABUF_BYTES;
        const uint32_t bb = bs_base + buf * ABUF_BYTES;
#pragma unroll
        for (int ks = 0; ks < 4; ks++) {
            const uint32_t kkb = ks * 32;   // 16 halfs * 2B
            uint32_t af[2][4];
#pragma unroll
            for (int mt = 0; mt < 2; mt++)
                ldsm_x4(af[mt], ab + a_off[mt] + kkb);
            uint32_t bf[8][2];
#pragma unroll
            for (int ntp = 0; ntp < 4; ntp++) {
                uint32_t qd[4];
                ldsm_x4(qd, bb + b_off[ntp] + kkb);
                bf[2 * ntp][0]     = qd[0]; bf[2 * ntp][1]     = qd[1];
                bf[2 * ntp + 1][0] = qd[2]; bf[2 * ntp + 1][1] = qd[3];
            }
#pragma unroll
            for (int mt = 0; mt < 2; mt++)
#pragma unroll
                for (int nt = 0; nt < 8; nt++)
                    mma_f16(acc[mt][nt], af[mt], bf[nt]);
        }
        __syncthreads();
    }

    // Epilogue: bias (+residual fp32/fp16, +ReLU) -> fp32 or fp16 output
#pragma unroll
    for (int mt = 0; mt < 2; mt++) {
        const int r0 = bm * 128 + warp_m * 32 + mt * 16 + gid;
#pragma unroll
        for (int nt = 0; nt < 8; nt++) {
            const int col = bn * 128 + warp_n * 64 + nt * 8 + 2 * ctid;
            const float b0 = bias[col], b1 = bias[col + 1];
            float2 v0, v1;
            v0.x = acc[mt][nt][0] + b0; v0.y = acc[mt][nt][1] + b1;
            v1.x = acc[mt][nt][2] + b0; v1.y = acc[mt][nt][3] + b1;
            const size_t base0 = (size_t)r0 * N + col;
            const size_t base1 = (size_t)(r0 + 8) * N + col;
            if (Radd) {
                float2 ra = *(const float2*)(Radd + base0);
                float2 rb = *(const float2*)(Radd + base1);
                v0.x += ra.x; v0.y += ra.y;
                v1.x += rb.x; v1.y += rb.y;
            }
            if (RaddH) {
                float2 ra = __half22float2(*(const __half2*)(RaddH + base0));
                float2 rb = __half22float2(*(const __half2*)(RaddH + base1));
                v0.x += ra.x; v0.y += ra.y;
                v1.x += rb.x; v1.y += rb.y;
            }
            if (relu) {
                v0.x = fmaxf(v0.x, 0.f); v0.y = fmaxf(v0.y, 0.f);
                v1.x = fmaxf(v1.x, 0.f); v1.y = fmaxf(v1.y, 0.f);
            }
            if (Cf) {
                *(float2*)(Cf + base0) = v0;
                *(float2*)(Cf + base1) = v1;
            } else {
                __half2 h0 = __floats2half2_rn(v0.x, v0.y);
                __half2 h1 = __floats2half2_rn(v1.x, v1.y);
                *(__half2*)(Ch + base0) = h0;
                *(__half2*)(Ch + base1) = h1;
            }
        }
    }
}

// ---------------------------------------------------------------------------
// Window attention, half2 smem edition.
// Reads packed qkv [TOK, 1536], writes oh [TOK, 512].
// One block per (window, head); 256 threads. All smem tiles stored as
// __half2 with row stride 33 (conflict-free for stores and both loops);
// math in fp32.
// ---------------------------------------------------------------------------
#define HSTR 33   // half2 per row (32 data + 1 pad)

__global__ __launch_bounds__(256) void window_attn_kernel(
    const __half* __restrict__ qkv, __half* __restrict__ o)
{
    const int bid = blockIdx.x;
    const int h = bid & (NHEAD - 1);
    const int w = bid >> 3;
    const int t0 = w * WIN;
    const int tid = threadIdx.x;

    __shared__ __half2 qs2[WIN * HSTR];
    __shared__ __half2 ks2[WIN * HSTR];
    __shared__ __half2 vs2[WIN * HSTR];
    __shared__ float   sc[WIN][WIN + 1];

    // Load q/k/v tiles: 32 rows x 64 halfs each; thread loads 8 halfs/tile.
    {
        const int row = tid >> 3;            // 0..31
        const int hb = (tid & 7) * 4;        // half2 col base 0..28
        const size_t base = (size_t)(t0 + row) * DQKV + h * DH + (tid & 7) * 8;
        uint4 uq = *(const uint4*)(qkv + base);
        uint4 uk = *(const uint4*)(qkv + base + DM);
        uint4 uv = *(const uint4*)(qkv + base + 2 * DM);
        const __half2* hq = (const __half2*)&uq;
        const __half2* hk = (const __half2*)&uk;
        const __half2* hv = (const __half2*)&uv;
#pragma unroll
        for (int j = 0; j < 4; j++) {
            qs2[row * HSTR + hb + j] = hq[j];
            ks2[row * HSTR + hb + j] = hk[j];
            vs2[row * HSTR + hb + j] = hv[j];
        }
    }
    __syncthreads();

    // Scores: 1024 entries / 256 threads = 4 each; 32 half2 per dot.
#pragma unroll
    for (int i = 0; i < 4; i++) {
        int lin = tid + i * 256;
        int r = lin >> 5, c = lin & 31;
        float s = 0.f;
#pragma unroll
        for (int dd = 0; dd < 32; dd++) {
            float2 fq = __half22float2(qs2[r * HSTR + dd]);   // broadcast
            float2 fk = __half22float2(ks2[c * HSTR + dd]);   // conflict-free
            s += fq.x * fk.x + fq.y * fk.y;
        }
        sc[r][c] = s * 0.125f;
    }
    __syncthreads();

    // Softmax per row
    if (tid < WIN) {
        float m = -1e30f;
#pragma unroll
        for (int j = 0; j < WIN; j++) m = fmaxf(m, sc[tid][j]);
        float sum = 0.f;
#pragma unroll
        for (int j = 0; j < WIN; j++) {
            float e = __expf(sc[tid][j] - m);
            sc[tid][j] = e;
            sum += e;
        }
        float inv = 1.0f / sum;
#pragma unroll
        for (int j = 0; j < WIN; j++) sc[tid][j] *= inv;
    }
    __syncthreads();

    // O = attn @ V: 1024 half2 outputs / 256 threads = 4 each.
#pragma unroll
    for (int i = 0; i < 4; i++) {
        int lin = tid + i * 256;
        int r = lin >> 5, dd = lin & 31;     // half2 column
        float s0 = 0.f, s1 = 0.f;
#pragma unroll
        for (int j = 0; j < WIN; j++) {
            float a = sc[r][j];               // broadcast
            float2 fv = __half22float2(vs2[j * HSTR + dd]);   // conflict-free
            s0 += a * fv.x;
            s1 += a * fv.y;
        }
        *(__half2*)(o + (size_t)(t0 + r) * DM + h * DH + dd * 2) =
            __floats2half2_rn(s0, s1);
    }
}

// ---------------------------------------------------------------------------
// LayerNorm over a pre-summed row. One block (128 threads) per token row.
// Optional fp32 output y and/or fp16 output yh.
// ---------------------------------------------------------------------------
__global__ __launch_bounds__(128) void ln_kernel(
    const float* __restrict__ xr,
    const float* __restrict__ g, const float* __restrict__ b,
    float* __restrict__ y, __half* __restrict__ yh)
{
    const int row = blockIdx.x;
    const int tid = threadIdx.x;

    float4 xv = ((const float4*)(xr + (size_t)row * DM))[tid];
    float v0 = xv.x, v1 = xv.y, v2 = xv.z, v3 = xv.w;

    __shared__ float red[4];
    float s = v0 + v1 + v2 + v3;
#pragma unroll
    for (int off = 16; off > 0; off >>= 1) s += __shfl_xor_sync(0xffffffffu, s, off);
    if ((tid & 31) == 0) red[tid >> 5] = s;
    __syncthreads();
    const float mu = (red[0] + red[1] + red[2] + red[3]) * (1.0f / DM);

    float d0 = v0 - mu, d1 = v1 - mu, d2 = v2 - mu, d3 = v3 - mu;
    float qsum = d0 * d0 + d1 * d1 + d2 * d2 + d3 * d3;
    __syncthreads();
#pragma unroll
    for (int off = 16; off > 0; off >>= 1) qsum += __shfl_xor_sync(0xffffffffu, qsum, off);
    if ((tid & 31) == 0) red[tid >> 5] = qsum;
    __syncthreads();
    const float var = (red[0] + red[1] + red[2] + red[3]) * (1.0f / DM);
    const float inv = rsqrtf(var + EPSLN);

    float4 gv = ((const float4*)g)[tid];
    float4 bv = ((const float4*)b)[tid];
    float4 out;
    out.x = d0 * inv * gv.x + bv.x;
    out.y = d1 * inv * gv.y + bv.y;
    out.z = d2 * inv * gv.z + bv.z;
    out.w = d3 * inv * gv.w + bv.w;
    if (y)
        ((float4*)(y + (size_t)row * DM))[tid] = out;
    if (yh) {
        __half2 h0 = __floats2half2_rn(out.x, out.y);
        __half2 h1 = __floats2half2_rn(out.z, out.w);
        uint2 u;
        u.x = *(uint32_t*)&h0;
        u.y = *(uint32_t*)&h1;
        ((uint2*)(yh + (size_t)row * DM))[tid] = u;
    }
}

// ---------------------------------------------------------------------------
// Launch
// ---------------------------------------------------------------------------
extern "C" void kernel_launch(void* const* d_in, const int* in_sizes, int n_in,
                              void* d_out, int out_size)
{
    (void)in_sizes; (void)n_in; (void)out_size;
    const float* x   = (const float*)d_in[0];
    const float* Wq  = (const float*)d_in[1];
    const float* bq  = (const float*)d_in[2];
    const float* Wk  = (const float*)d_in[3];
    const float* bk  = (const float*)d_in[4];
    const float* Wv  = (const float*)d_in[5];
    const float* bv  = (const float*)d_in[6];
    const float* Wo  = (const float*)d_in[7];
    const float* bo  = (const float*)d_in[8];
    const float* g1  = (const float*)d_in[9];
    const float* be1 = (const float*)d_in[10];
    const float* W1  = (const float*)d_in[11];
    const float* b1  = (const float*)d_in[12];
    const float* W2  = (const float*)d_in[13];
    const float* b2  = (const float*)d_in[14];
    const float* g2  = (const float*)d_in[15];
    const float* be2 = (const float*)d_in[16];
    float* out = (float*)d_out;

    __half *xh, *qkvh, *oh, *x1h, *hh;
    float *f32a, *bqkv;
    __half *wqkvt, *wot, *w1t, *w2t;
    cudaGetSymbolAddress((void**)&xh,    g_xh);
    cudaGetSymbolAddress((void**)&qkvh,  g_qkvh);
    cudaGetSymbolAddress((void**)&oh,    g_oh);
    cudaGetSymbolAddress((void**)&x1h,   g_x1h);
    cudaGetSymbolAddress((void**)&hh,    g_hh);
    cudaGetSymbolAddress((void**)&f32a,  g_f32a);
    cudaGetSymbolAddress((void**)&wqkvt, g_wqkvt);
    cudaGetSymbolAddress((void**)&wot,   g_wot);
    cudaGetSymbolAddress((void**)&w1t,   g_w1t);
    cudaGetSymbolAddress((void**)&w2t,   g_w2t);
    cudaGetSymbolAddress((void**)&bqkv,  g_bqkv);

    cudaFuncSetAttribute(h16_gemm_kernel,
                         cudaFuncAttributeMaxDynamicSharedMemorySize, GEMM_SMEM);

    // Prep: x fp16 convert + all weight transposes + bias concat (2 launches)
    f2h_kernel<<<(TOK * DM / 4) / 256, 256>>>(x, xh);
    prep_kernel<<<3073, dim3(32, 8)>>>(Wq, Wk, Wv, Wo, W1, W2,
                                       wqkvt, wot, w1t, w2t,
                                       bq, bk, bv, bqkv);

    dim3 gQKV(DQKV / 128, TOK / 128);  // (12, 512)
    dim3 gD  (DM   / 128, TOK / 128);  // (4, 512)
    dim3 gFF (DFF  / 128, TOK / 128);  // (16, 512)

    // Fused QKV projection -> qkvh [TOK, 1536] (fp16)
    h16_gemm_kernel<<<gQKV, 256, GEMM_SMEM>>>(xh, wqkvt, bqkv, nullptr, nullptr,
                                              nullptr, qkvh, TOK, DQKV, DM, 0);

    // Block-local window attention (half2 smem)
    window_attn_kernel<<<NWIN * NHEAD, 256>>>(qkvh, oh);

    // Output projection + residual(x, fp32) -> f32a = x + attn_out
    h16_gemm_kernel<<<gD, 256, GEMM_SMEM>>>(oh, wot, bo, x, nullptr,
                                            f32a, nullptr, TOK, DM, DM, 0);

    // LN1 -> x1h (fp16 only)
    ln_kernel<<<TOK, 128>>>(f32a, g1, be1, nullptr, x1h);

    // FFN
    h16_gemm_kernel<<<gFF, 256, GEMM_SMEM>>>(x1h, w1t, b1, nullptr, nullptr,
                                             nullptr, hh, TOK, DFF, DM, 1);
    // W2 + residual(x1h, fp16) -> f32a = x1 + ff_out
    h16_gemm_kernel<<<gD, 256, GEMM_SMEM>>>(hh, w2t, b2, nullptr, x1h,
                                            f32a, nullptr, TOK, DM, DFF, 0);

    // LN2 -> output (fp32)
    ln_kernel<<<TOK, 128>>>(f32a, g2, be2, out, nullptr);
}

// round 13
// speedup vs baseline: 1.2527x; 1.1081x over previous
#include <cuda_runtime.h>
#include <cuda_fp16.h>
#include <cstdint>

// Problem constants
#define TOK   65536      // B*S = 8*8192
#define DM    512
#define DQKV  1536
#define DFF   2048
#define NHEAD 8
#define DH    64
#define WIN   32
#define NWIN  2048       // TOK/WIN
#define EPSLN 1e-5f

// ---------------------------------------------------------------------------
// Scratch (device globals; allocation-free per harness rules)
// ---------------------------------------------------------------------------
__device__ __half g_xh  [(size_t)TOK * DM];
__device__ __half g_qkvh[(size_t)TOK * DQKV];
__device__ __half g_oh  [(size_t)TOK * DM];
__device__ __half g_x1h [(size_t)TOK * DM];
__device__ __half g_hh  [(size_t)TOK * DFF];
__device__ float  g_f32a[(size_t)TOK * DM];   // x+attn_out, then x1+ff_out
// Transposed (N-major) fp16 weights
__device__ __half g_wqkvt[(size_t)DQKV * DM];
__device__ __half g_wot  [DM * DM];
__device__ __half g_w1t  [(size_t)DFF * DM];
__device__ __half g_w2t  [(size_t)DM * DFF];
__device__ float  g_bqkv [DQKV];

// ---------------------------------------------------------------------------
// fp32 -> fp16 convert (x)
// ---------------------------------------------------------------------------
__global__ void f2h_kernel(const float* __restrict__ x, __half* __restrict__ xh)
{
    size_t i = (size_t)blockIdx.x * blockDim.x + threadIdx.x;
    float4 v = ((const float4*)x)[i];
    __half2 h0 = __floats2half2_rn(v.x, v.y);
    __half2 h1 = __floats2half2_rn(v.z, v.w);
    uint2 u;
    u.x = *(uint32_t*)&h0;
    u.y = *(uint32_t*)&h1;
    ((uint2*)xh)[i] = u;
}

// ---------------------------------------------------------------------------
// Fused prep: all 6 weight transposes (fp32->fp16) + qkv bias concat.
// ---------------------------------------------------------------------------
__global__ void prep_kernel(
    const float* __restrict__ Wq, const float* __restrict__ Wk,
    const float* __restrict__ Wv, const float* __restrict__ Wo,
    const float* __restrict__ W1, const float* __restrict__ W2,
    __half* __restrict__ wqkvt, __half* __restrict__ wot,
    __half* __restrict__ w1t, __half* __restrict__ w2t,
    const float* __restrict__ bq, const float* __restrict__ bk,
    const float* __restrict__ bv, float* __restrict__ bqkv)
{
    const int t = blockIdx.x;
    const int tx = threadIdx.x, ty = threadIdx.y;

    if (t >= 3072) {   // bias concat
        const int tid = ty * 32 + tx;
        for (int i = tid; i < DQKV; i += 256) {
            const float* src = (i < DM) ? bq : (i < 2 * DM) ? bk : bv;
            bqkv[i] = src[i & (DM - 1)];
        }
        return;
    }

    const float* W;
    __half* Wt;
    int K, N, idx;
    if (t < 1024) {
        const int m = t >> 8;
        idx = t & 255;
        K = DM; N = DM;
        W  = (m == 0) ? Wq : (m == 1) ? Wk : (m == 2) ? Wv : Wo;
        Wt = (m == 0) ? wqkvt
           : (m == 1) ? (wqkvt + 512 * DM)
           : (m == 2) ? (wqkvt + 1024 * DM) : wot;
    } else if (t < 2048) {
        idx = t - 1024; W = W1; Wt = w1t; K = DM; N = DFF;
    } else {
        idx = t - 2048; W = W2; Wt = w2t; K = DFF; N = DM;
    }
    const int ntx = N / 32;
    const int n0 = (idx % ntx) * 32, k0 = (idx / ntx) * 32;

    __shared__ float tb[32][33];
#pragma unroll
    for (int i = ty; i < 32; i += 8)
        tb[i][tx] = W[(size_t)(k0 + i) * N + n0 + tx];
    __syncthreads();
#pragma unroll
    for (int i = ty; i < 32; i += 8)
        Wt[(size_t)(n0 + i) * K + k0 + tx] = __float2half_rn(tb[tx][i]);
}

// ---------------------------------------------------------------------------
// Shared mma / ldmatrix helpers
// ---------------------------------------------------------------------------
__device__ __forceinline__ void ldsm_x4(uint32_t r[4], uint32_t addr)
{
    asm volatile("ldmatrix.sync.aligned.m8n8.x4.shared.b16 {%0,%1,%2,%3}, [%4];"
                 : "=r"(r[0]), "=r"(r[1]), "=r"(r[2]), "=r"(r[3]) : "r"(addr));
}

__device__ __forceinline__ void mma_f16(float c[4], const uint32_t a[4],
                                        const uint32_t b[2])
{
    asm volatile(
        "mma.sync.aligned.m16n8k16.row.col.f32.f16.f16.f32 "
        "{%0,%1,%2,%3}, {%4,%5,%6,%7}, {%8,%9}, {%0,%1,%2,%3};"
        : "+f"(c[0]), "+f"(c[1]), "+f"(c[2]), "+f"(c[3])
        : "r"(a[0]), "r"(a[1]), "r"(a[2]), "r"(a[3]), "r"(b[0]), "r"(b[1]));
}

__device__ __forceinline__ void cp16(uint32_t smem, const __half* gmem)
{
    asm volatile("cp.async.cg.shared.global [%0], [%1], 16;"
                 :: "r"(smem), "l"(gmem));
}

__device__ __forceinline__ uint32_t pack_h2(float x, float y)
{
    __half2 t = __floats2half2_rn(x, y);
    return *(uint32_t*)&t;
}

// ---------------------------------------------------------------------------
// FP16 tensor-core GEMM (proven config): CTA 128x128, BK=64, 2-stage cp.async,
// 8 warps of 32x64, mma.sync.m16n8k16, 72KB smem, 2 CTAs/SM.
// ---------------------------------------------------------------------------
#define GBK 64
#define HSTRIDE 72
#define ABUF_BYTES (128 * HSTRIDE * 2)
#define GEMM_SMEM (4 * ABUF_BYTES)

__global__ __launch_bounds__(256, 2) void h16_gemm_kernel(
    const __half* __restrict__ A, const __half* __restrict__ Bt,
    const float* __restrict__ bias,
    const float* __restrict__ Radd, const __half* __restrict__ RaddH,
    float* __restrict__ Cf, __half* __restrict__ Ch,
    int M, int N, int K, int relu)
{
    extern __shared__ __half smem_dyn[];

    const int tid = threadIdx.x;
    const int bm = blockIdx.y, bn = blockIdx.x;
    const int wid = tid >> 5, lane = tid & 31;
    const int warp_m = wid & 3;
    const int warp_n = wid >> 2;
    const int gid = lane >> 2, ctid = lane & 3;
    const int mat = lane >> 3, rin = lane & 7;

    const uint32_t as_base = (uint32_t)__cvta_generic_to_shared(smem_dyn);
    const uint32_t bs_base = as_base + 2 * ABUF_BYTES;

    int ldr[4], ldc[4];
#pragma unroll
    for (int i = 0; i < 4; i++) {
        int c = tid + i * 256;
        ldr[i] = c >> 3;
        ldc[i] = (c & 7) * 8;
    }

    uint32_t a_off[2], b_off[4];
#pragma unroll
    for (int mt = 0; mt < 2; mt++)
        a_off[mt] = ((warp_m * 32 + mt * 16 + (mat & 1) * 8 + rin) * HSTRIDE
                     + (mat >> 1) * 8) * 2;
#pragma unroll
    for (int ntp = 0; ntp < 4; ntp++)
        b_off[ntp] = ((warp_n * 64 + ntp * 16 + (mat >> 1) * 8 + rin) * HSTRIDE
                      + (mat & 1) * 8) * 2;

    float acc[2][8][4];
#pragma unroll
    for (int mt = 0; mt < 2; mt++)
#pragma unroll
        for (int nt = 0; nt < 8; nt++)
#pragma unroll
            for (int i = 0; i < 4; i++) acc[mt][nt][i] = 0.0f;

    const __half* Abase = A  + (size_t)(bm * 128) * K;
    const __half* Bbase = Bt + (size_t)(bn * 128) * K;
    const int ntiles = K / GBK;

    {
#pragma unroll
        for (int i = 0; i < 4; i++) {
            cp16(as_base + (ldr[i] * HSTRIDE + ldc[i]) * 2,
                 Abase + (size_t)ldr[i] * K + ldc[i]);
            cp16(bs_base + (ldr[i] * HSTRIDE + ldc[i]) * 2,
                 Bbase + (size_t)ldr[i] * K + ldc[i]);
        }
        asm volatile("cp.async.commit_group;");
    }

    for (int t = 0; t < ntiles; t++) {
        const int buf = t & 1;
        if (t + 1 < ntiles) {
            const int nb = buf ^ 1;
            const int k0 = (t + 1) * GBK;
            const __half* Ap = Abase + k0;
            const __half* Bp = Bbase + k0;
            const uint32_t ao = as_base + nb * ABUF_BYTES;
            const uint32_t bo = bs_base + nb * ABUF_BYTES;
#pragma unroll
            for (int i = 0; i < 4; i++) {
                cp16(ao + (ldr[i] * HSTRIDE + ldc[i]) * 2,
                     Ap + (size_t)ldr[i] * K + ldc[i]);
                cp16(bo + (ldr[i] * HSTRIDE + ldc[i]) * 2,
                     Bp + (size_t)ldr[i] * K + ldc[i]);
            }
            asm volatile("cp.async.commit_group;");
            asm volatile("cp.async.wait_group 1;");
        } else {
            asm volatile("cp.async.wait_group 0;");
        }
        __syncthreads();

        const uint32_t ab = as_base + buf * ABUF_BYTES;
        const uint32_t bb = bs_base + buf * ABUF_BYTES;
#pragma unroll
        for (int ks = 0; ks < 4; ks++) {
            const uint32_t kkb = ks * 32;
            uint32_t af[2][4];
#pragma unroll
            for (int mt = 0; mt < 2; mt++)
                ldsm_x4(af[mt], ab + a_off[mt] + kkb);
            uint32_t bf[8][2];
#pragma unroll
            for (int ntp = 0; ntp < 4; ntp++) {
                uint32_t qd[4];
                ldsm_x4(qd, bb + b_off[ntp] + kkb);
                bf[2 * ntp][0]     = qd[0]; bf[2 * ntp][1]     = qd[1];
                bf[2 * ntp + 1][0] = qd[2]; bf[2 * ntp + 1][1] = qd[3];
            }
#pragma unroll
            for (int mt = 0; mt < 2; mt++)
#pragma unroll
                for (int nt = 0; nt < 8; nt++)
                    mma_f16(acc[mt][nt], af[mt], bf[nt]);
        }
        __syncthreads();
    }

#pragma unroll
    for (int mt = 0; mt < 2; mt++) {
        const int r0 = bm * 128 + warp_m * 32 + mt * 16 + gid;
#pragma unroll
        for (int nt = 0; nt < 8; nt++) {
            const int col = bn * 128 + warp_n * 64 + nt * 8 + 2 * ctid;
            const float b0 = bias[col], b1 = bias[col + 1];
            float2 v0, v1;
            v0.x = acc[mt][nt][0] + b0; v0.y = acc[mt][nt][1] + b1;
            v1.x = acc[mt][nt][2] + b0; v1.y = acc[mt][nt][3] + b1;
            const size_t base0 = (size_t)r0 * N + col;
            const size_t base1 = (size_t)(r0 + 8) * N + col;
            if (Radd) {
                float2 ra = *(const float2*)(Radd + base0);
                float2 rb = *(const float2*)(Radd + base1);
                v0.x += ra.x; v0.y += ra.y;
                v1.x += rb.x; v1.y += rb.y;
            }
            if (RaddH) {
                float2 ra = __half22float2(*(const __half2*)(RaddH + base0));
                float2 rb = __half22float2(*(const __half2*)(RaddH + base1));
                v0.x += ra.x; v0.y += ra.y;
                v1.x += rb.x; v1.y += rb.y;
            }
            if (relu) {
                v0.x = fmaxf(v0.x, 0.f); v0.y = fmaxf(v0.y, 0.f);
                v1.x = fmaxf(v1.x, 0.f); v1.y = fmaxf(v1.y, 0.f);
            }
            if (Cf) {
                *(float2*)(Cf + base0) = v0;
                *(float2*)(Cf + base1) = v1;
            } else {
                __half2 h0 = __floats2half2_rn(v0.x, v0.y);
                __half2 h1 = __floats2half2_rn(v1.x, v1.y);
                *(__half2*)(Ch + base0) = h0;
                *(__half2*)(Ch + base1) = h1;
            }
        }
    }
}

// ---------------------------------------------------------------------------
// Window attention via mma.sync. One warp per (window, head); 4 warps/block.
// Per-warp smem: Q[32][72], K[32][72], vT[64][40] halfs (7168 halfs).
// S = Q·K^T via mma (GEMM-proven fragment layout); softmax in registers
// (shfl over the 4 lanes owning each row); P stays in registers as the
// A-fragment of O = P·V (accumulator->A-fragment identity mapping); O staged
// through the dead Q buffer for coalesced stores.
// ---------------------------------------------------------------------------
#define AW_WARP_H 7168                      // halfs per warp
#define AW_SMEM  (4 * AW_WARP_H * 2)        // 57344 B per block

__global__ __launch_bounds__(128, 2) void window_attn_kernel(
    const __half* __restrict__ qkv, __half* __restrict__ o)
{
    extern __shared__ __half sbuf[];
    const int tid = threadIdx.x;
    const int wid = tid >> 5, lane = tid & 31;
    const int w = blockIdx.x >> 1;
    const int h = ((blockIdx.x & 1) << 2) + wid;
    const int t0 = w * WIN;

    __half* sQ  = sbuf + wid * AW_WARP_H;
    __half* sK  = sQ + 2304;                 // 32*72
    __half* sVT = sQ + 4608;                 // 64 rows * 40

    const int gid = lane >> 2, ctid = lane & 3;
    const int mat = lane >> 3, rin = lane & 7;

    // Load Q,K (row-major, stride 72) and V transposed (vT[d][j], stride 40)
#pragma unroll
    for (int i = 0; i < 8; i++) {
        const int c = lane + (i << 5);       // 0..255
        const int row = c >> 3, c8 = c & 7;
        const size_t gb = (size_t)(t0 + row) * DQKV + h * DH + (c8 << 3);
        *(uint4*)(sQ + row * 72 + (c8 << 3)) = *(const uint4*)(qkv + gb);
        *(uint4*)(sK + row * 72 + (c8 << 3)) = *(const uint4*)(qkv + gb + DM);
        uint4 uv = *(const uint4*)(qkv + gb + 2 * DM);
        const __half* hv = (const __half*)&uv;
#pragma unroll
        for (int d = 0; d < 8; d++)
            sVT[((c8 << 3) + d) * 40 + row] = hv[d];
    }
    __syncwarp();

    const uint32_t sQb = (uint32_t)__cvta_generic_to_shared(sQ);
    const uint32_t sKb = (uint32_t)__cvta_generic_to_shared(sK);
    const uint32_t sVb = (uint32_t)__cvta_generic_to_shared(sVT);

    uint32_t a_off[2], bk_off[2], bv_off[4];
#pragma unroll
    for (int mt = 0; mt < 2; mt++)
        a_off[mt] = sQb + ((mt * 16 + (mat & 1) * 8 + rin) * 72
                           + (mat >> 1) * 8) * 2;
#pragma unroll
    for (int np = 0; np < 2; np++)
        bk_off[np] = sKb + ((np * 16 + (mat >> 1) * 8 + rin) * 72
                            + (mat & 1) * 8) * 2;
#pragma unroll
    for (int np = 0; np < 4; np++)
        bv_off[np] = sVb + ((np * 16 + (mat >> 1) * 8 + rin) * 40
                            + (mat & 1) * 8) * 2;

    // ---- S = Q @ K^T  (M=32, N=32, K=64) ----
    float e[2][4][4];
#pragma unroll
    for (int mt = 0; mt < 2; mt++)
#pragma unroll
        for (int nt = 0; nt < 4; nt++)
#pragma unroll
            for (int i = 0; i < 4; i++) e[mt][nt][i] = 0.0f;

#pragma unroll
    for (int ks = 0; ks < 4; ks++) {
        const uint32_t kkb = ks * 32;
        uint32_t af[2][4];
        ldsm_x4(af[0], a_off[0] + kkb);
        ldsm_x4(af[1], a_off[1] + kkb);
        uint32_t bf[4][2];
#pragma unroll
        for (int np = 0; np < 2; np++) {
            uint32_t qd[4];
            ldsm_x4(qd, bk_off[np] + kkb);
            bf[2 * np][0]     = qd[0]; bf[2 * np][1]     = qd[1];
            bf[2 * np + 1][0] = qd[2]; bf[2 * np + 1][1] = qd[3];
        }
#pragma unroll
        for (int mt = 0; mt < 2; mt++)
#pragma unroll
            for (int nt = 0; nt < 4; nt++)
                mma_f16(e[mt][nt], af[mt], bf[nt]);
    }

    // ---- softmax per row, registers + shfl over the 4 owning lanes ----
#pragma unroll
    for (int mt = 0; mt < 2; mt++) {
        float mxA = -1e30f, mxB = -1e30f;
#pragma unroll
        for (int nt = 0; nt < 4; nt++) {
#pragma unroll
            for (int i = 0; i < 4; i++) e[mt][nt][i] *= 0.125f;
            mxA = fmaxf(mxA, fmaxf(e[mt][nt][0], e[mt][nt][1]));
            mxB = fmaxf(mxB, fmaxf(e[mt][nt][2], e[mt][nt][3]));
        }
        mxA = fmaxf(mxA, __shfl_xor_sync(0xffffffffu, mxA, 1));
        mxA = fmaxf(mxA, __shfl_xor_sync(0xffffffffu, mxA, 2));
        mxB = fmaxf(mxB, __shfl_xor_sync(0xffffffffu, mxB, 1));
        mxB = fmaxf(mxB, __shfl_xor_sync(0xffffffffu, mxB, 2));
        float suA = 0.f, suB = 0.f;
#pragma unroll
        for (int nt = 0; nt < 4; nt++) {
            e[mt][nt][0] = __expf(e[mt][nt][0] - mxA);
            e[mt][nt][1] = __expf(e[mt][nt][1] - mxA);
            e[mt][nt][2] = __expf(e[mt][nt][2] - mxB);
            e[mt][nt][3] = __expf(e[mt][nt][3] - mxB);
            suA += e[mt][nt][0] + e[mt][nt][1];
            suB += e[mt][nt][2] + e[mt][nt][3];
        }
        suA += __shfl_xor_sync(0xffffffffu, suA, 1);
        suA += __shfl_xor_sync(0xffffffffu, suA, 2);
        suB += __shfl_xor_sync(0xffffffffu, suB, 1);
        suB += __shfl_xor_sync(0xffffffffu, suB, 2);
        const float ivA = 1.0f / suA, ivB = 1.0f / suB;
#pragma unroll
        for (int nt = 0; nt < 4; nt++) {
            e[mt][nt][0] *= ivA; e[mt][nt][1] *= ivA;
            e[mt][nt][2] *= ivB; e[mt][nt][3] *= ivB;
        }
    }

    // ---- O = P @ V  (M=32, N=64, K=32), P from registers ----
    float acc_o[2][8][4];
#pragma unroll
    for (int mt = 0; mt < 2; mt++)
#pragma unroll
        for (int nt = 0; nt < 8; nt++)
#pragma unroll
            for (int i = 0; i < 4; i++) acc_o[mt][nt][i] = 0.0f;

#pragma unroll
    for (int kt = 0; kt < 2; kt++) {
        uint32_t bv[8][2];
#pragma unroll
        for (int np = 0; np < 4; np++) {
            uint32_t qd[4];
            ldsm_x4(qd, bv_off[np] + kt * 32);
            bv[2 * np][0]     = qd[0]; bv[2 * np][1]     = qd[1];
            bv[2 * np + 1][0] = qd[2]; bv[2 * np + 1][1] = qd[3];
        }
#pragma unroll
        for (int mt = 0; mt < 2; mt++) {
            uint32_t a[4];
            a[0] = pack_h2(e[mt][2 * kt][0],     e[mt][2 * kt][1]);
            a[1] = pack_h2(e[mt][2 * kt][2],     e[mt][2 * kt][3]);
            a[2] = pack_h2(e[mt][2 * kt + 1][0], e[mt][2 * kt + 1][1]);
            a[3] = pack_h2(e[mt][2 * kt + 1][2], e[mt][2 * kt + 1][3]);
#pragma unroll
            for (int nt = 0; nt < 8; nt++)
                mma_f16(acc_o[mt][nt], a, bv[kt == 0 ? nt : nt]);
        }
    }

    // ---- epilogue: stage O through sQ (dead) for coalesced writes ----
    __syncwarp();
#pragma unroll
    for (int mt = 0; mt < 2; mt++)
#pragma unroll
        for (int nt = 0; nt < 8; nt++) {
            const int col = nt * 8 + 2 * ctid;
            *(__half2*)(sQ + (mt * 16 + gid) * 72 + col) =
                __floats2half2_rn(acc_o[mt][nt][0], acc_o[mt][nt][1]);
            *(__half2*)(sQ + (mt * 16 + gid + 8) * 72 + col) =
                __floats2half2_rn(acc_o[mt][nt][2], acc_o[mt][nt][3]);
        }
    __syncwarp();
#pragma unroll
    for (int i = 0; i < 8; i++) {
        const int c = lane + (i << 5);
        const int row = c >> 3, c8 = c & 7;
        *(uint4*)(o + (size_t)(t0 + row) * DM + h * DH + (c8 << 3)) =
            *(const uint4*)(sQ + row * 72 + (c8 << 3));
    }
}

// ---------------------------------------------------------------------------
// LayerNorm over a pre-summed row. One block (128 threads) per token row.
// ---------------------------------------------------------------------------
__global__ __launch_bounds__(128) void ln_kernel(
    const float* __restrict__ xr,
    const float* __restrict__ g, const float* __restrict__ b,
    float* __restrict__ y, __half* __restrict__ yh)
{
    const int row = blockIdx.x;
    const int tid = threadIdx.x;

    float4 xv = ((const float4*)(xr + (size_t)row * DM))[tid];
    float v0 = xv.x, v1 = xv.y, v2 = xv.z, v3 = xv.w;

    __shared__ float red[4];
    float s = v0 + v1 + v2 + v3;
#pragma unroll
    for (int off = 16; off > 0; off >>= 1) s += __shfl_xor_sync(0xffffffffu, s, off);
    if ((tid & 31) == 0) red[tid >> 5] = s;
    __syncthreads();
    const float mu = (red[0] + red[1] + red[2] + red[3]) * (1.0f / DM);

    float d0 = v0 - mu, d1 = v1 - mu, d2 = v2 - mu, d3 = v3 - mu;
    float qsum = d0 * d0 + d1 * d1 + d2 * d2 + d3 * d3;
    __syncthreads();
#pragma unroll
    for (int off = 16; off > 0; off >>= 1) qsum += __shfl_xor_sync(0xffffffffu, qsum, off);
    if ((tid & 31) == 0) red[tid >> 5] = qsum;
    __syncthreads();
    const float var = (red[0] + red[1] + red[2] + red[3]) * (1.0f / DM);
    const float inv = rsqrtf(var + EPSLN);

    float4 gv = ((const float4*)g)[tid];
    float4 bv = ((const float4*)b)[tid];
    float4 out;
    out.x = d0 * inv * gv.x + bv.x;
    out.y = d1 * inv * gv.y + bv.y;
    out.z = d2 * inv * gv.z + bv.z;
    out.w = d3 * inv * gv.w + bv.w;
    if (y)
        ((float4*)(y + (size_t)row * DM))[tid] = out;
    if (yh) {
        __half2 h0 = __floats2half2_rn(out.x, out.y);
        __half2 h1 = __floats2half2_rn(out.z, out.w);
        uint2 u;
        u.x = *(uint32_t*)&h0;
        u.y = *(uint32_t*)&h1;
        ((uint2*)(yh + (size_t)row * DM))[tid] = u;
    }
}

// ---------------------------------------------------------------------------
// Launch
// ---------------------------------------------------------------------------
extern "C" void kernel_launch(void* const* d_in, const int* in_sizes, int n_in,
                              void* d_out, int out_size)
{
    (void)in_sizes; (void)n_in; (void)out_size;
    const float* x   = (const float*)d_in[0];
    const float* Wq  = (const float*)d_in[1];
    const float* bq  = (const float*)d_in[2];
    const float* Wk  = (const float*)d_in[3];
    const float* bk  = (const float*)d_in[4];
    const float* Wv  = (const float*)d_in[5];
    const float* bv  = (const float*)d_in[6];
    const float* Wo  = (const float*)d_in[7];
    const float* bo  = (const float*)d_in[8];
    const float* g1  = (const float*)d_in[9];
    const float* be1 = (const float*)d_in[10];
    const float* W1  = (const float*)d_in[11];
    const float* b1  = (const float*)d_in[12];
    const float* W2  = (const float*)d_in[13];
    const float* b2  = (const float*)d_in[14];
    const float* g2  = (const float*)d_in[15];
    const float* be2 = (const float*)d_in[16];
    float* out = (float*)d_out;

    __half *xh, *qkvh, *oh, *x1h, *hh;
    float *f32a, *bqkv;
    __half *wqkvt, *wot, *w1t, *w2t;
    cudaGetSymbolAddress((void**)&xh,    g_xh);
    cudaGetSymbolAddress((void**)&qkvh,  g_qkvh);
    cudaGetSymbolAddress((void**)&oh,    g_oh);
    cudaGetSymbolAddress((void**)&x1h,   g_x1h);
    cudaGetSymbolAddress((void**)&hh,    g_hh);
    cudaGetSymbolAddress((void**)&f32a,  g_f32a);
    cudaGetSymbolAddress((void**)&wqkvt, g_wqkvt);
    cudaGetSymbolAddress((void**)&wot,   g_wot);
    cudaGetSymbolAddress((void**)&w1t,   g_w1t);
    cudaGetSymbolAddress((void**)&w2t,   g_w2t);
    cudaGetSymbolAddress((void**)&bqkv,  g_bqkv);

    cudaFuncSetAttribute(h16_gemm_kernel,
                         cudaFuncAttributeMaxDynamicSharedMemorySize, GEMM_SMEM);
    cudaFuncSetAttribute(window_attn_kernel,
                         cudaFuncAttributeMaxDynamicSharedMemorySize, AW_SMEM);

    // Prep: x fp16 convert + all weight transposes + bias concat (2 launches)
    f2h_kernel<<<(TOK * DM / 4) / 256, 256>>>(x, xh);
    prep_kernel<<<3073, dim3(32, 8)>>>(Wq, Wk, Wv, Wo, W1, W2,
                                       wqkvt, wot, w1t, w2t,
                                       bq, bk, bv, bqkv);

    dim3 gQKV(DQKV / 128, TOK / 128);  // (12, 512)
    dim3 gD  (DM   / 128, TOK / 128);  // (4, 512)
    dim3 gFF (DFF  / 128, TOK / 128);  // (16, 512)

    // Fused QKV projection -> qkvh [TOK, 1536] (fp16)
    h16_gemm_kernel<<<gQKV, 256, GEMM_SMEM>>>(xh, wqkvt, bqkv, nullptr, nullptr,
                                              nullptr, qkvh, TOK, DQKV, DM, 0);

    // Block-local window attention (mma.sync; warp per window-head)
    window_attn_kernel<<<NWIN * 2, 128, AW_SMEM>>>(qkvh, oh);

    // Output projection + residual(x, fp32) -> f32a = x + attn_out
    h16_gemm_kernel<<<gD, 256, GEMM_SMEM>>>(oh, wot, bo, x, nullptr,
                                            f32a, nullptr, TOK, DM, DM, 0);

    // LN1 -> x1h (fp16 only)
    ln_kernel<<<TOK, 128>>>(f32a, g1, be1, nullptr, x1h);

    // FFN
    h16_gemm_kernel<<<gFF, 256, GEMM_SMEM>>>(x1h, w1t, b1, nullptr, nullptr,
                                             nullptr, hh, TOK, DFF, DM, 1);
    // W2 + residual(x1h, fp16) -> f32a = x1 + ff_out
    h16_gemm_kernel<<<gD, 256, GEMM_SMEM>>>(hh, w2t, b2, nullptr, x1h,
                                            f32a, nullptr, TOK, DM, DFF, 0);

    // LN2 -> output (fp32)
    ln_kernel<<<TOK, 128>>>(f32a, g2, be2, out, nullptr);
}

// round 14
// speedup vs baseline: 1.2629x; 1.0081x over previous
#include <cuda_runtime.h>
#include <cuda_fp16.h>
#include <cstdint>

// Problem constants
#define TOK   65536      // B*S = 8*8192
#define DM    512
#define DQKV  1536
#define DFF   2048
#define NHEAD 8
#define DH    64
#define WIN   32
#define NWIN  2048       // TOK/WIN
#define EPSLN 1e-5f

// ---------------------------------------------------------------------------
// Scratch (device globals; allocation-free per harness rules)
// ---------------------------------------------------------------------------
__device__ __half g_xh  [(size_t)TOK * DM];
__device__ __half g_qkvh[(size_t)TOK * DQKV];
__device__ __half g_oh  [(size_t)TOK * DM];
__device__ __half g_x1h [(size_t)TOK * DM];
__device__ __half g_hh  [(size_t)TOK * DFF];
__device__ float  g_f32a[(size_t)TOK * DM];   // reused as fp16 residual buffer
// Transposed (N-major) fp16 weights
__device__ __half g_wqkvt[(size_t)DQKV * DM];
__device__ __half g_wot  [DM * DM];
__device__ __half g_w1t  [(size_t)DFF * DM];
__device__ __half g_w2t  [(size_t)DM * DFF];
__device__ float  g_bqkv [DQKV];

// ---------------------------------------------------------------------------
// fp32 -> fp16 convert (x)
// ---------------------------------------------------------------------------
__global__ void f2h_kernel(const float* __restrict__ x, __half* __restrict__ xh)
{
    size_t i = (size_t)blockIdx.x * blockDim.x + threadIdx.x;
    float4 v = ((const float4*)x)[i];
    __half2 h0 = __floats2half2_rn(v.x, v.y);
    __half2 h1 = __floats2half2_rn(v.z, v.w);
    uint2 u;
    u.x = *(uint32_t*)&h0;
    u.y = *(uint32_t*)&h1;
    ((uint2*)xh)[i] = u;
}

// ---------------------------------------------------------------------------
// Fused prep: all 6 weight transposes (fp32->fp16) + qkv bias concat.
// ---------------------------------------------------------------------------
__global__ void prep_kernel(
    const float* __restrict__ Wq, const float* __restrict__ Wk,
    const float* __restrict__ Wv, const float* __restrict__ Wo,
    const float* __restrict__ W1, const float* __restrict__ W2,
    __half* __restrict__ wqkvt, __half* __restrict__ wot,
    __half* __restrict__ w1t, __half* __restrict__ w2t,
    const float* __restrict__ bq, const float* __restrict__ bk,
    const float* __restrict__ bv, float* __restrict__ bqkv)
{
    const int t = blockIdx.x;
    const int tx = threadIdx.x, ty = threadIdx.y;

    if (t >= 3072) {   // bias concat
        const int tid = ty * 32 + tx;
        for (int i = tid; i < DQKV; i += 256) {
            const float* src = (i < DM) ? bq : (i < 2 * DM) ? bk : bv;
            bqkv[i] = src[i & (DM - 1)];
        }
        return;
    }

    const float* W;
    __half* Wt;
    int K, N, idx;
    if (t < 1024) {
        const int m = t >> 8;
        idx = t & 255;
        K = DM; N = DM;
        W  = (m == 0) ? Wq : (m == 1) ? Wk : (m == 2) ? Wv : Wo;
        Wt = (m == 0) ? wqkvt
           : (m == 1) ? (wqkvt + 512 * DM)
           : (m == 2) ? (wqkvt + 1024 * DM) : wot;
    } else if (t < 2048) {
        idx = t - 1024; W = W1; Wt = w1t; K = DM; N = DFF;
    } else {
        idx = t - 2048; W = W2; Wt = w2t; K = DFF; N = DM;
    }
    const int ntx = N / 32;
    const int n0 = (idx % ntx) * 32, k0 = (idx / ntx) * 32;

    __shared__ float tb[32][33];
#pragma unroll
    for (int i = ty; i < 32; i += 8)
        tb[i][tx] = W[(size_t)(k0 + i) * N + n0 + tx];
    __syncthreads();
#pragma unroll
    for (int i = ty; i < 32; i += 8)
        Wt[(size_t)(n0 + i) * K + k0 + tx] = __float2half_rn(tb[tx][i]);
}

// ---------------------------------------------------------------------------
// Shared mma / ldmatrix helpers
// ---------------------------------------------------------------------------
__device__ __forceinline__ void ldsm_x4(uint32_t r[4], uint32_t addr)
{
    asm volatile("ldmatrix.sync.aligned.m8n8.x4.shared.b16 {%0,%1,%2,%3}, [%4];"
                 : "=r"(r[0]), "=r"(r[1]), "=r"(r[2]), "=r"(r[3]) : "r"(addr));
}

__device__ __forceinline__ void mma_f16(float c[4], const uint32_t a[4],
                                        const uint32_t b[2])
{
    asm volatile(
        "mma.sync.aligned.m16n8k16.row.col.f32.f16.f16.f32 "
        "{%0,%1,%2,%3}, {%4,%5,%6,%7}, {%8,%9}, {%0,%1,%2,%3};"
        : "+f"(c[0]), "+f"(c[1]), "+f"(c[2]), "+f"(c[3])
        : "r"(a[0]), "r"(a[1]), "r"(a[2]), "r"(a[3]), "r"(b[0]), "r"(b[1]));
}

__device__ __forceinline__ void cp16(uint32_t smem, const __half* gmem)
{
    asm volatile("cp.async.cg.shared.global [%0], [%1], 16;"
                 :: "r"(smem), "l"(gmem));
}

__device__ __forceinline__ uint32_t pack_h2(float x, float y)
{
    __half2 t = __floats2half2_rn(x, y);
    return *(uint32_t*)&t;
}

// ---------------------------------------------------------------------------
// FP16 tensor-core GEMM (proven config): CTA 128x128, BK=64, 2-stage cp.async,
// 8 warps of 32x64, mma.sync.m16n8k16, 72KB smem, 2 CTAs/SM.
// K is compile-time: K = NTILES*64.
// ---------------------------------------------------------------------------
#define GBK 64
#define HSTRIDE 72
#define ABUF_BYTES (128 * HSTRIDE * 2)
#define GEMM_SMEM (4 * ABUF_BYTES)

template<int NTILES>
__global__ __launch_bounds__(256, 2) void h16_gemm_kernel(
    const __half* __restrict__ A, const __half* __restrict__ Bt,
    const float* __restrict__ bias,
    const float* __restrict__ Radd, const __half* __restrict__ RaddH,
    float* __restrict__ Cf, __half* __restrict__ Ch,
    int M, int N, int relu)
{
    constexpr int K = NTILES * GBK;
    extern __shared__ __half smem_dyn[];

    const int tid = threadIdx.x;
    const int bm = blockIdx.y, bn = blockIdx.x;
    const int wid = tid >> 5, lane = tid & 31;
    const int warp_m = wid & 3;
    const int warp_n = wid >> 2;
    const int gid = lane >> 2, ctid = lane & 3;
    const int mat = lane >> 3, rin = lane & 7;

    const uint32_t as_base = (uint32_t)__cvta_generic_to_shared(smem_dyn);
    const uint32_t bs_base = as_base + 2 * ABUF_BYTES;

    int ldr[4], ldc[4];
#pragma unroll
    for (int i = 0; i < 4; i++) {
        int c = tid + i * 256;
        ldr[i] = c >> 3;
        ldc[i] = (c & 7) * 8;
    }

    uint32_t a_off[2], b_off[4];
#pragma unroll
    for (int mt = 0; mt < 2; mt++)
        a_off[mt] = ((warp_m * 32 + mt * 16 + (mat & 1) * 8 + rin) * HSTRIDE
                     + (mat >> 1) * 8) * 2;
#pragma unroll
    for (int ntp = 0; ntp < 4; ntp++)
        b_off[ntp] = ((warp_n * 64 + ntp * 16 + (mat >> 1) * 8 + rin) * HSTRIDE
                      + (mat & 1) * 8) * 2;

    float acc[2][8][4];
#pragma unroll
    for (int mt = 0; mt < 2; mt++)
#pragma unroll
        for (int nt = 0; nt < 8; nt++)
#pragma unroll
            for (int i = 0; i < 4; i++) acc[mt][nt][i] = 0.0f;

    const __half* Abase = A  + (size_t)(bm * 128) * K;
    const __half* Bbase = Bt + (size_t)(bn * 128) * K;

    // Prologue: tile 0 -> stage 0
    {
#pragma unroll
        for (int i = 0; i < 4; i++) {
            cp16(as_base + (ldr[i] * HSTRIDE + ldc[i]) * 2,
                 Abase + (size_t)ldr[i] * K + ldc[i]);
            cp16(bs_base + (ldr[i] * HSTRIDE + ldc[i]) * 2,
                 Bbase + (size_t)ldr[i] * K + ldc[i]);
        }
        asm volatile("cp.async.commit_group;");
    }

#pragma unroll 2
    for (int t = 0; t < NTILES; t++) {
        const int buf = t & 1;
        if (t + 1 < NTILES) {
            const int nb = buf ^ 1;
            const int k0 = (t + 1) * GBK;
            const __half* Ap = Abase + k0;
            const __half* Bp = Bbase + k0;
            const uint32_t ao = as_base + nb * ABUF_BYTES;
            const uint32_t bo = bs_base + nb * ABUF_BYTES;
#pragma unroll
            for (int i = 0; i < 4; i++) {
                cp16(ao + (ldr[i] * HSTRIDE + ldc[i]) * 2,
                     Ap + (size_t)ldr[i] * K + ldc[i]);
                cp16(bo + (ldr[i] * HSTRIDE + ldc[i]) * 2,
                     Bp + (size_t)ldr[i] * K + ldc[i]);
            }
            asm volatile("cp.async.commit_group;");
            asm volatile("cp.async.wait_group 1;");
        } else {
            asm volatile("cp.async.wait_group 0;");
        }
        __syncthreads();

        const uint32_t ab = as_base + buf * ABUF_BYTES;
        const uint32_t bb = bs_base + buf * ABUF_BYTES;
#pragma unroll
        for (int ks = 0; ks < 4; ks++) {
            const uint32_t kkb = ks * 32;
            uint32_t af[2][4];
#pragma unroll
            for (int mt = 0; mt < 2; mt++)
                ldsm_x4(af[mt], ab + a_off[mt] + kkb);
            uint32_t bf[8][2];
#pragma unroll
            for (int ntp = 0; ntp < 4; ntp++) {
                uint32_t qd[4];
                ldsm_x4(qd, bb + b_off[ntp] + kkb);
                bf[2 * ntp][0]     = qd[0]; bf[2 * ntp][1]     = qd[1];
                bf[2 * ntp + 1][0] = qd[2]; bf[2 * ntp + 1][1] = qd[3];
            }
#pragma unroll
            for (int mt = 0; mt < 2; mt++)
#pragma unroll
                for (int nt = 0; nt < 8; nt++)
                    mma_f16(acc[mt][nt], af[mt], bf[nt]);
        }
        __syncthreads();
    }

    // Epilogue: bias (+residual fp32/fp16, +ReLU) -> fp32 or fp16 output
#pragma unroll
    for (int mt = 0; mt < 2; mt++) {
        const int r0 = bm * 128 + warp_m * 32 + mt * 16 + gid;
#pragma unroll
        for (int nt = 0; nt < 8; nt++) {
            const int col = bn * 128 + warp_n * 64 + nt * 8 + 2 * ctid;
            const float b0 = bias[col], b1 = bias[col + 1];
            float2 v0, v1;
            v0.x = acc[mt][nt][0] + b0; v0.y = acc[mt][nt][1] + b1;
            v1.x = acc[mt][nt][2] + b0; v1.y = acc[mt][nt][3] + b1;
            const size_t base0 = (size_t)r0 * N + col;
            const size_t base1 = (size_t)(r0 + 8) * N + col;
            if (Radd) {
                float2 ra = *(const float2*)(Radd + base0);
                float2 rb = *(const float2*)(Radd + base1);
                v0.x += ra.x; v0.y += ra.y;
                v1.x += rb.x; v1.y += rb.y;
            }
            if (RaddH) {
                float2 ra = __half22float2(*(const __half2*)(RaddH + base0));
                float2 rb = __half22float2(*(const __half2*)(RaddH + base1));
                v0.x += ra.x; v0.y += ra.y;
                v1.x += rb.x; v1.y += rb.y;
            }
            if (relu) {
                v0.x = fmaxf(v0.x, 0.f); v0.y = fmaxf(v0.y, 0.f);
                v1.x = fmaxf(v1.x, 0.f); v1.y = fmaxf(v1.y, 0.f);
            }
            if (Cf) {
                *(float2*)(Cf + base0) = v0;
                *(float2*)(Cf + base1) = v1;
            } else {
                __half2 h0 = __floats2half2_rn(v0.x, v0.y);
                __half2 h1 = __floats2half2_rn(v1.x, v1.y);
                *(__half2*)(Ch + base0) = h0;
                *(__half2*)(Ch + base1) = h1;
            }
        }
    }
}

// ---------------------------------------------------------------------------
// Window attention via mma.sync (proven R13 kernel). One warp per
// (window, head); 4 warps/block; register softmax; P in registers.
// ---------------------------------------------------------------------------
#define AW_WARP_H 7168
#define AW_SMEM  (4 * AW_WARP_H * 2)

__global__ __launch_bounds__(128, 2) void window_attn_kernel(
    const __half* __restrict__ qkv, __half* __restrict__ o)
{
    extern __shared__ __half sbuf[];
    const int tid = threadIdx.x;
    const int wid = tid >> 5, lane = tid & 31;
    const int w = blockIdx.x >> 1;
    const int h = ((blockIdx.x & 1) << 2) + wid;
    const int t0 = w * WIN;

    __half* sQ  = sbuf + wid * AW_WARP_H;
    __half* sK  = sQ + 2304;
    __half* sVT = sQ + 4608;

    const int gid = lane >> 2, ctid = lane & 3;
    const int mat = lane >> 3, rin = lane & 7;

#pragma unroll
    for (int i = 0; i < 8; i++) {
        const int c = lane + (i << 5);
        const int row = c >> 3, c8 = c & 7;
        const size_t gb = (size_t)(t0 + row) * DQKV + h * DH + (c8 << 3);
        *(uint4*)(sQ + row * 72 + (c8 << 3)) = *(const uint4*)(qkv + gb);
        *(uint4*)(sK + row * 72 + (c8 << 3)) = *(const uint4*)(qkv + gb + DM);
        uint4 uv = *(const uint4*)(qkv + gb + 2 * DM);
        const __half* hv = (const __half*)&uv;
#pragma unroll
        for (int d = 0; d < 8; d++)
            sVT[((c8 << 3) + d) * 40 + row] = hv[d];
    }
    __syncwarp();

    const uint32_t sQb = (uint32_t)__cvta_generic_to_shared(sQ);
    const uint32_t sKb = (uint32_t)__cvta_generic_to_shared(sK);
    const uint32_t sVb = (uint32_t)__cvta_generic_to_shared(sVT);

    uint32_t a_off[2], bk_off[2], bv_off[4];
#pragma unroll
    for (int mt = 0; mt < 2; mt++)
        a_off[mt] = sQb + ((mt * 16 + (mat & 1) * 8 + rin) * 72
                           + (mat >> 1) * 8) * 2;
#pragma unroll
    for (int np = 0; np < 2; np++)
        bk_off[np] = sKb + ((np * 16 + (mat >> 1) * 8 + rin) * 72
                            + (mat & 1) * 8) * 2;
#pragma unroll
    for (int np = 0; np < 4; np++)
        bv_off[np] = sVb + ((np * 16 + (mat >> 1) * 8 + rin) * 40
                            + (mat & 1) * 8) * 2;

    float e[2][4][4];
#pragma unroll
    for (int mt = 0; mt < 2; mt++)
#pragma unroll
        for (int nt = 0; nt < 4; nt++)
#pragma unroll
            for (int i = 0; i < 4; i++) e[mt][nt][i] = 0.0f;

#pragma unroll
    for (int ks = 0; ks < 4; ks++) {
        const uint32_t kkb = ks * 32;
        uint32_t af[2][4];
        ldsm_x4(af[0], a_off[0] + kkb);
        ldsm_x4(af[1], a_off[1] + kkb);
        uint32_t bf[4][2];
#pragma unroll
        for (int np = 0; np < 2; np++) {
            uint32_t qd[4];
            ldsm_x4(qd, bk_off[np] + kkb);
            bf[2 * np][0]     = qd[0]; bf[2 * np][1]     = qd[1];
            bf[2 * np + 1][0] = qd[2]; bf[2 * np + 1][1] = qd[3];
        }
#pragma unroll
        for (int mt = 0; mt < 2; mt++)
#pragma unroll
            for (int nt = 0; nt < 4; nt++)
                mma_f16(e[mt][nt], af[mt], bf[nt]);
    }

#pragma unroll
    for (int mt = 0; mt < 2; mt++) {
        float mxA = -1e30f, mxB = -1e30f;
#pragma unroll
        for (int nt = 0; nt < 4; nt++) {
#pragma unroll
            for (int i = 0; i < 4; i++) e[mt][nt][i] *= 0.125f;
            mxA = fmaxf(mxA, fmaxf(e[mt][nt][0], e[mt][nt][1]));
            mxB = fmaxf(mxB, fmaxf(e[mt][nt][2], e[mt][nt][3]));
        }
        mxA = fmaxf(mxA, __shfl_xor_sync(0xffffffffu, mxA, 1));
        mxA = fmaxf(mxA, __shfl_xor_sync(0xffffffffu, mxA, 2));
        mxB = fmaxf(mxB, __shfl_xor_sync(0xffffffffu, mxB, 1));
        mxB = fmaxf(mxB, __shfl_xor_sync(0xffffffffu, mxB, 2));
        float suA = 0.f, suB = 0.f;
#pragma unroll
        for (int nt = 0; nt < 4; nt++) {
            e[mt][nt][0] = __expf(e[mt][nt][0] - mxA);
            e[mt][nt][1] = __expf(e[mt][nt][1] - mxA);
            e[mt][nt][2] = __expf(e[mt][nt][2] - mxB);
            e[mt][nt][3] = __expf(e[mt][nt][3] - mxB);
            suA += e[mt][nt][0] + e[mt][nt][1];
            suB += e[mt][nt][2] + e[mt][nt][3];
        }
        suA += __shfl_xor_sync(0xffffffffu, suA, 1);
        suA += __shfl_xor_sync(0xffffffffu, suA, 2);
        suB += __shfl_xor_sync(0xffffffffu, suB, 1);
        suB += __shfl_xor_sync(0xffffffffu, suB, 2);
        const float ivA = 1.0f / suA, ivB = 1.0f / suB;
#pragma unroll
        for (int nt = 0; nt < 4; nt++) {
            e[mt][nt][0] *= ivA; e[mt][nt][1] *= ivA;
            e[mt][nt][2] *= ivB; e[mt][nt][3] *= ivB;
        }
    }

    float acc_o[2][8][4];
#pragma unroll
    for (int mt = 0; mt < 2; mt++)
#pragma unroll
        for (int nt = 0; nt < 8; nt++)
#pragma unroll
            for (int i = 0; i < 4; i++) acc_o[mt][nt][i] = 0.0f;

#pragma unroll
    for (int kt = 0; kt < 2; kt++) {
        uint32_t bv[8][2];
#pragma unroll
        for (int np = 0; np < 4; np++) {
            uint32_t qd[4];
            ldsm_x4(qd, bv_off[np] + kt * 32);
            bv[2 * np][0]     = qd[0]; bv[2 * np][1]     = qd[1];
            bv[2 * np + 1][0] = qd[2]; bv[2 * np + 1][1] = qd[3];
        }
#pragma unroll
        for (int mt = 0; mt < 2; mt++) {
            uint32_t a[4];
            a[0] = pack_h2(e[mt][2 * kt][0],     e[mt][2 * kt][1]);
            a[1] = pack_h2(e[mt][2 * kt][2],     e[mt][2 * kt][3]);
            a[2] = pack_h2(e[mt][2 * kt + 1][0], e[mt][2 * kt + 1][1]);
            a[3] = pack_h2(e[mt][2 * kt + 1][2], e[mt][2 * kt + 1][3]);
#pragma unroll
            for (int nt = 0; nt < 8; nt++)
                mma_f16(acc_o[mt][nt], a, bv[nt]);
        }
    }

    __syncwarp();
#pragma unroll
    for (int mt = 0; mt < 2; mt++)
#pragma unroll
        for (int nt = 0; nt < 8; nt++) {
            const int col = nt * 8 + 2 * ctid;
            *(__half2*)(sQ + (mt * 16 + gid) * 72 + col) =
                __floats2half2_rn(acc_o[mt][nt][0], acc_o[mt][nt][1]);
            *(__half2*)(sQ + (mt * 16 + gid + 8) * 72 + col) =
                __floats2half2_rn(acc_o[mt][nt][2], acc_o[mt][nt][3]);
        }
    __syncwarp();
#pragma unroll
    for (int i = 0; i < 8; i++) {
        const int c = lane + (i << 5);
        const int row = c >> 3, c8 = c & 7;
        *(uint4*)(o + (size_t)(t0 + row) * DM + h * DH + (c8 << 3)) =
            *(const uint4*)(sQ + row * 72 + (c8 << 3));
    }
}

// ---------------------------------------------------------------------------
// LayerNorm over a pre-summed fp16 row. One block (128 threads) per token.
// Optional fp32 output y and/or fp16 output yh.
// ---------------------------------------------------------------------------
__global__ __launch_bounds__(128) void ln_h_kernel(
    const __half* __restrict__ xr,
    const float* __restrict__ g, const float* __restrict__ b,
    float* __restrict__ y, __half* __restrict__ yh)
{
    const int row = blockIdx.x;
    const int tid = threadIdx.x;

    uint2 u = ((const uint2*)(xr + (size_t)row * DM))[tid];   // 4 halfs
    float2 f0 = __half22float2(*(__half2*)&u.x);
    float2 f1 = __half22float2(*(__half2*)&u.y);
    float v0 = f0.x, v1 = f0.y, v2 = f1.x, v3 = f1.y;

    __shared__ float red[4];
    float s = v0 + v1 + v2 + v3;
#pragma unroll
    for (int off = 16; off > 0; off >>= 1) s += __shfl_xor_sync(0xffffffffu, s, off);
    if ((tid & 31) == 0) red[tid >> 5] = s;
    __syncthreads();
    const float mu = (red[0] + red[1] + red[2] + red[3]) * (1.0f / DM);

    float d0 = v0 - mu, d1 = v1 - mu, d2 = v2 - mu, d3 = v3 - mu;
    float qsum = d0 * d0 + d1 * d1 + d2 * d2 + d3 * d3;
    __syncthreads();
#pragma unroll
    for (int off = 16; off > 0; off >>= 1) qsum += __shfl_xor_sync(0xffffffffu, qsum, off);
    if ((tid & 31) == 0) red[tid >> 5] = qsum;
    __syncthreads();
    const float var = (red[0] + red[1] + red[2] + red[3]) * (1.0f / DM);
    const float inv = rsqrtf(var + EPSLN);

    float4 gv = ((const float4*)g)[tid];
    float4 bv = ((const float4*)b)[tid];
    float4 out;
    out.x = d0 * inv * gv.x + bv.x;
    out.y = d1 * inv * gv.y + bv.y;
    out.z = d2 * inv * gv.z + bv.z;
    out.w = d3 * inv * gv.w + bv.w;
    if (y)
        ((float4*)(y + (size_t)row * DM))[tid] = out;
    if (yh) {
        __half2 h0 = __floats2half2_rn(out.x, out.y);
        __half2 h1 = __floats2half2_rn(out.z, out.w);
        uint2 uo;
        uo.x = *(uint32_t*)&h0;
        uo.y = *(uint32_t*)&h1;
        ((uint2*)(yh + (size_t)row * DM))[tid] = uo;
    }
}

// ---------------------------------------------------------------------------
// Launch
// ---------------------------------------------------------------------------
extern "C" void kernel_launch(void* const* d_in, const int* in_sizes, int n_in,
                              void* d_out, int out_size)
{
    (void)in_sizes; (void)n_in; (void)out_size;
    const float* x   = (const float*)d_in[0];
    const float* Wq  = (const float*)d_in[1];
    const float* bq  = (const float*)d_in[2];
    const float* Wk  = (const float*)d_in[3];
    const float* bk  = (const float*)d_in[4];
    const float* Wv  = (const float*)d_in[5];
    const float* bv  = (const float*)d_in[6];
    const float* Wo  = (const float*)d_in[7];
    const float* bo  = (const float*)d_in[8];
    const float* g1  = (const float*)d_in[9];
    const float* be1 = (const float*)d_in[10];
    const float* W1  = (const float*)d_in[11];
    const float* b1  = (const float*)d_in[12];
    const float* W2  = (const float*)d_in[13];
    const float* b2  = (const float*)d_in[14];
    const float* g2  = (const float*)d_in[15];
    const float* be2 = (const float*)d_in[16];
    float* out = (float*)d_out;

    __half *xh, *qkvh, *oh, *x1h, *hh;
    float *f32a, *bqkv;
    __half *wqkvt, *wot, *w1t, *w2t;
    cudaGetSymbolAddress((void**)&xh,    g_xh);
    cudaGetSymbolAddress((void**)&qkvh,  g_qkvh);
    cudaGetSymbolAddress((void**)&oh,    g_oh);
    cudaGetSymbolAddress((void**)&x1h,   g_x1h);
    cudaGetSymbolAddress((void**)&hh,    g_hh);
    cudaGetSymbolAddress((void**)&f32a,  g_f32a);
    cudaGetSymbolAddress((void**)&wqkvt, g_wqkvt);
    cudaGetSymbolAddress((void**)&wot,   g_wot);
    cudaGetSymbolAddress((void**)&w1t,   g_w1t);
    cudaGetSymbolAddress((void**)&w2t,   g_w2t);
    cudaGetSymbolAddress((void**)&bqkv,  g_bqkv);
    __half* resh = (__half*)f32a;   // fp16 residual-sum buffer (aliases f32a)

    cudaFuncSetAttribute(h16_gemm_kernel<8>,
                         cudaFuncAttributeMaxDynamicSharedMemorySize, GEMM_SMEM);
    cudaFuncSetAttribute(h16_gemm_kernel<32>,
                         cudaFuncAttributeMaxDynamicSharedMemorySize, GEMM_SMEM);
    cudaFuncSetAttribute(window_attn_kernel,
                         cudaFuncAttributeMaxDynamicSharedMemorySize, AW_SMEM);

    // Prep: x fp16 convert + all weight transposes + bias concat (2 launches)
    f2h_kernel<<<(TOK * DM / 4) / 256, 256>>>(x, xh);
    prep_kernel<<<3073, dim3(32, 8)>>>(Wq, Wk, Wv, Wo, W1, W2,
                                       wqkvt, wot, w1t, w2t,
                                       bq, bk, bv, bqkv);

    dim3 gQKV(DQKV / 128, TOK / 128);  // (12, 512)
    dim3 gD  (DM   / 128, TOK / 128);  // (4, 512)
    dim3 gFF (DFF  / 128, TOK / 128);  // (16, 512)

    // Fused QKV projection -> qkvh [TOK, 1536] (fp16); K=512
    h16_gemm_kernel<8><<<gQKV, 256, GEMM_SMEM>>>(xh, wqkvt, bqkv, nullptr,
                                                 nullptr, nullptr, qkvh,
                                                 TOK, DQKV, 0);

    // Block-local window attention (mma.sync)
    window_attn_kernel<<<NWIN * 2, 128, AW_SMEM>>>(qkvh, oh);

    // Output projection + residual(x, fp32) -> resh = fp16(x + attn_out); K=512
    h16_gemm_kernel<8><<<gD, 256, GEMM_SMEM>>>(oh, wot, bo, x, nullptr,
                                               nullptr, resh, TOK, DM, 0);

    // LN1 (fp16 in) -> x1h (fp16)
    ln_h_kernel<<<TOK, 128>>>(resh, g1, be1, nullptr, x1h);

    // FFN: W1 (K=512, ReLU) -> hh fp16
    h16_gemm_kernel<8><<<gFF, 256, GEMM_SMEM>>>(x1h, w1t, b1, nullptr, nullptr,
                                                nullptr, hh, TOK, DFF, 1);
    // W2 (K=2048) + residual(x1h) -> resh = fp16(x1 + ff_out)
    h16_gemm_kernel<32><<<gD, 256, GEMM_SMEM>>>(hh, w2t, b2, nullptr, x1h,
                                                nullptr, resh, TOK, DM, 0);

    // LN2 (fp16 in) -> output (fp32)
    ln_h_kernel<<<TOK, 128>>>(resh, g2, be2, out, nullptr);
}

// round 15
// speedup vs baseline: 1.2822x; 1.0153x over previous
#include <cuda_runtime.h>
#include <cuda_fp16.h>
#include <cstdint>

// Problem constants
#define TOK   65536      // B*S = 8*8192
#define DM    512
#define DQKV  1536
#define DFF   2048
#define NHEAD 8
#define DH    64
#define WIN   32
#define NWIN  2048       // TOK/WIN
#define EPSLN 1e-5f

// ---------------------------------------------------------------------------
// Scratch (device globals; allocation-free per harness rules)
// ---------------------------------------------------------------------------
__device__ __half g_xh  [(size_t)TOK * DM];
__device__ __half g_qkvh[(size_t)TOK * DQKV];
__device__ __half g_oh  [(size_t)TOK * DM];
__device__ __half g_x1h [(size_t)TOK * DM];
__device__ __half g_hh  [(size_t)TOK * DFF];
__device__ float  g_f32a[(size_t)TOK * DM];   // reused as fp16 residual buffer
// Transposed (N-major) fp16 weights
__device__ __half g_wqkvt[(size_t)DQKV * DM];
__device__ __half g_wot  [DM * DM];
__device__ __half g_w1t  [(size_t)DFF * DM];
__device__ __half g_w2t  [(size_t)DM * DFF];
__device__ float  g_bqkv [DQKV];

// ---------------------------------------------------------------------------
// fp32 -> fp16 convert (x)
// ---------------------------------------------------------------------------
__global__ void f2h_kernel(const float* __restrict__ x, __half* __restrict__ xh)
{
    size_t i = (size_t)blockIdx.x * blockDim.x + threadIdx.x;
    float4 v = ((const float4*)x)[i];
    __half2 h0 = __floats2half2_rn(v.x, v.y);
    __half2 h1 = __floats2half2_rn(v.z, v.w);
    uint2 u;
    u.x = *(uint32_t*)&h0;
    u.y = *(uint32_t*)&h1;
    ((uint2*)xh)[i] = u;
}

// ---------------------------------------------------------------------------
// Fused prep: all 6 weight transposes (fp32->fp16) + qkv bias concat.
// ---------------------------------------------------------------------------
__global__ void prep_kernel(
    const float* __restrict__ Wq, const float* __restrict__ Wk,
    const float* __restrict__ Wv, const float* __restrict__ Wo,
    const float* __restrict__ W1, const float* __restrict__ W2,
    __half* __restrict__ wqkvt, __half* __restrict__ wot,
    __half* __restrict__ w1t, __half* __restrict__ w2t,
    const float* __restrict__ bq, const float* __restrict__ bk,
    const float* __restrict__ bv, float* __restrict__ bqkv)
{
    const int t = blockIdx.x;
    const int tx = threadIdx.x, ty = threadIdx.y;

    if (t >= 3072) {   // bias concat
        const int tid = ty * 32 + tx;
        for (int i = tid; i < DQKV; i += 256) {
            const float* src = (i < DM) ? bq : (i < 2 * DM) ? bk : bv;
            bqkv[i] = src[i & (DM - 1)];
        }
        return;
    }

    const float* W;
    __half* Wt;
    int K, N, idx;
    if (t < 1024) {
        const int m = t >> 8;
        idx = t & 255;
        K = DM; N = DM;
        W  = (m == 0) ? Wq : (m == 1) ? Wk : (m == 2) ? Wv : Wo;
        Wt = (m == 0) ? wqkvt
           : (m == 1) ? (wqkvt + 512 * DM)
           : (m == 2) ? (wqkvt + 1024 * DM) : wot;
    } else if (t < 2048) {
        idx = t - 1024; W = W1; Wt = w1t; K = DM; N = DFF;
    } else {
        idx = t - 2048; W = W2; Wt = w2t; K = DFF; N = DM;
    }
    const int ntx = N / 32;
    const int n0 = (idx % ntx) * 32, k0 = (idx / ntx) * 32;

    __shared__ float tb[32][33];
#pragma unroll
    for (int i = ty; i < 32; i += 8)
        tb[i][tx] = W[(size_t)(k0 + i) * N + n0 + tx];
    __syncthreads();
#pragma unroll
    for (int i = ty; i < 32; i += 8)
        Wt[(size_t)(n0 + i) * K + k0 + tx] = __float2half_rn(tb[tx][i]);
}

// ---------------------------------------------------------------------------
// Shared mma / ldmatrix helpers
// ---------------------------------------------------------------------------
__device__ __forceinline__ void ldsm_x4(uint32_t r[4], uint32_t addr)
{
    asm volatile("ldmatrix.sync.aligned.m8n8.x4.shared.b16 {%0,%1,%2,%3}, [%4];"
                 : "=r"(r[0]), "=r"(r[1]), "=r"(r[2]), "=r"(r[3]) : "r"(addr));
}

__device__ __forceinline__ void mma_f16(float c[4], const uint32_t a[4],
                                        const uint32_t b[2])
{
    asm volatile(
        "mma.sync.aligned.m16n8k16.row.col.f32.f16.f16.f32 "
        "{%0,%1,%2,%3}, {%4,%5,%6,%7}, {%8,%9}, {%0,%1,%2,%3};"
        : "+f"(c[0]), "+f"(c[1]), "+f"(c[2]), "+f"(c[3])
        : "r"(a[0]), "r"(a[1]), "r"(a[2]), "r"(a[3]), "r"(b[0]), "r"(b[1]));
}

__device__ __forceinline__ void cp16(uint32_t smem, const __half* gmem)
{
    asm volatile("cp.async.cg.shared.global [%0], [%1], 16;"
                 :: "r"(smem), "l"(gmem));
}

__device__ __forceinline__ uint32_t pack_h2(float x, float y)
{
    __half2 t = __floats2half2_rn(x, y);
    return *(uint32_t*)&t;
}

// ---------------------------------------------------------------------------
// FP16 tensor-core GEMM: CTA tile 128x128, BK=64, 2-stage cp.async,
// *** 4 warps of 64x64 (block=128) *** to cut ldsm traffic 33%,
// mma.sync.m16n8k16, 72KB smem, 2 CTAs/SM. K compile-time = NTILES*64.
// ---------------------------------------------------------------------------
#define GBK 64
#define HSTRIDE 72
#define ABUF_BYTES (128 * HSTRIDE * 2)
#define GEMM_SMEM (4 * ABUF_BYTES)

template<int NTILES>
__global__ __launch_bounds__(128, 2) void h16_gemm_kernel(
    const __half* __restrict__ A, const __half* __restrict__ Bt,
    const float* __restrict__ bias,
    const float* __restrict__ Radd, const __half* __restrict__ RaddH,
    float* __restrict__ Cf, __half* __restrict__ Ch,
    int M, int N, int relu)
{
    constexpr int K = NTILES * GBK;
    extern __shared__ __half smem_dyn[];

    const int tid = threadIdx.x;
    const int bm = blockIdx.y, bn = blockIdx.x;
    const int wid = tid >> 5, lane = tid & 31;
    const int warp_m = wid & 1;          // 2 m-warps * 64 rows
    const int warp_n = wid >> 1;         // 2 n-warps * 64 cols
    const int gid = lane >> 2, ctid = lane & 3;
    const int mat = lane >> 3, rin = lane & 7;

    const uint32_t as_base = (uint32_t)__cvta_generic_to_shared(smem_dyn);
    const uint32_t bs_base = as_base + 2 * ABUF_BYTES;

    // cp.async indices: 1024 16B-chunks per tile per operand, 8 per thread
    int ldr[8], ldc[8];
#pragma unroll
    for (int i = 0; i < 8; i++) {
        int c = tid + i * 128;
        ldr[i] = c >> 3;
        ldc[i] = (c & 7) * 8;
    }

    // ldmatrix per-lane byte offsets (within a stage buffer), excluding k-step
    uint32_t a_off[4], b_off[4];
#pragma unroll
    for (int mt = 0; mt < 4; mt++)
        a_off[mt] = ((warp_m * 64 + mt * 16 + (mat & 1) * 8 + rin) * HSTRIDE
                     + (mat >> 1) * 8) * 2;
#pragma unroll
    for (int ntp = 0; ntp < 4; ntp++)
        b_off[ntp] = ((warp_n * 64 + ntp * 16 + (mat >> 1) * 8 + rin) * HSTRIDE
                      + (mat & 1) * 8) * 2;

    float acc[4][8][4];
#pragma unroll
    for (int mt = 0; mt < 4; mt++)
#pragma unroll
        for (int nt = 0; nt < 8; nt++)
#pragma unroll
            for (int i = 0; i < 4; i++) acc[mt][nt][i] = 0.0f;

    const __half* Abase = A  + (size_t)(bm * 128) * K;
    const __half* Bbase = Bt + (size_t)(bn * 128) * K;

    // Prologue: tile 0 -> stage 0
    {
#pragma unroll
        for (int i = 0; i < 8; i++) {
            cp16(as_base + (ldr[i] * HSTRIDE + ldc[i]) * 2,
                 Abase + (size_t)ldr[i] * K + ldc[i]);
            cp16(bs_base + (ldr[i] * HSTRIDE + ldc[i]) * 2,
                 Bbase + (size_t)ldr[i] * K + ldc[i]);
        }
        asm volatile("cp.async.commit_group;");
    }

#pragma unroll 2
    for (int t = 0; t < NTILES; t++) {
        const int buf = t & 1;
        if (t + 1 < NTILES) {
            const int nb = buf ^ 1;
            const int k0 = (t + 1) * GBK;
            const __half* Ap = Abase + k0;
            const __half* Bp = Bbase + k0;
            const uint32_t ao = as_base + nb * ABUF_BYTES;
            const uint32_t bo = bs_base + nb * ABUF_BYTES;
#pragma unroll
            for (int i = 0; i < 8; i++) {
                cp16(ao + (ldr[i] * HSTRIDE + ldc[i]) * 2,
                     Ap + (size_t)ldr[i] * K + ldc[i]);
                cp16(bo + (ldr[i] * HSTRIDE + ldc[i]) * 2,
                     Bp + (size_t)ldr[i] * K + ldc[i]);
            }
            asm volatile("cp.async.commit_group;");
            asm volatile("cp.async.wait_group 1;");
        } else {
            asm volatile("cp.async.wait_group 0;");
        }
        __syncthreads();

        const uint32_t ab = as_base + buf * ABUF_BYTES;
        const uint32_t bb = bs_base + buf * ABUF_BYTES;
#pragma unroll
        for (int ks = 0; ks < 4; ks++) {
            const uint32_t kkb = ks * 32;
            uint32_t af[4][4];
#pragma unroll
            for (int mt = 0; mt < 4; mt++)
                ldsm_x4(af[mt], ab + a_off[mt] + kkb);
            uint32_t bf[8][2];
#pragma unroll
            for (int ntp = 0; ntp < 4; ntp++) {
                uint32_t qd[4];
                ldsm_x4(qd, bb + b_off[ntp] + kkb);
                bf[2 * ntp][0]     = qd[0]; bf[2 * ntp][1]     = qd[1];
                bf[2 * ntp + 1][0] = qd[2]; bf[2 * ntp + 1][1] = qd[3];
            }
#pragma unroll
            for (int mt = 0; mt < 4; mt++)
#pragma unroll
                for (int nt = 0; nt < 8; nt++)
                    mma_f16(acc[mt][nt], af[mt], bf[nt]);
        }
        __syncthreads();
    }

    // Epilogue: bias (+residual fp32/fp16, +ReLU) -> fp32 or fp16 output
#pragma unroll
    for (int mt = 0; mt < 4; mt++) {
        const int r0 = bm * 128 + warp_m * 64 + mt * 16 + gid;
#pragma unroll
        for (int nt = 0; nt < 8; nt++) {
            const int col = bn * 128 + warp_n * 64 + nt * 8 + 2 * ctid;
            const float b0 = bias[col], b1 = bias[col + 1];
            float2 v0, v1;
            v0.x = acc[mt][nt][0] + b0; v0.y = acc[mt][nt][1] + b1;
            v1.x = acc[mt][nt][2] + b0; v1.y = acc[mt][nt][3] + b1;
            const size_t base0 = (size_t)r0 * N + col;
            const size_t base1 = (size_t)(r0 + 8) * N + col;
            if (Radd) {
                float2 ra = *(const float2*)(Radd + base0);
                float2 rb = *(const float2*)(Radd + base1);
                v0.x += ra.x; v0.y += ra.y;
                v1.x += rb.x; v1.y += rb.y;
            }
            if (RaddH) {
                float2 ra = __half22float2(*(const __half2*)(RaddH + base0));
                float2 rb = __half22float2(*(const __half2*)(RaddH + base1));
                v0.x += ra.x; v0.y += ra.y;
                v1.x += rb.x; v1.y += rb.y;
            }
            if (relu) {
                v0.x = fmaxf(v0.x, 0.f); v0.y = fmaxf(v0.y, 0.f);
                v1.x = fmaxf(v1.x, 0.f); v1.y = fmaxf(v1.y, 0.f);
            }
            if (Cf) {
                *(float2*)(Cf + base0) = v0;
                *(float2*)(Cf + base1) = v1;
            } else {
                __half2 h0 = __floats2half2_rn(v0.x, v0.y);
                __half2 h1 = __floats2half2_rn(v1.x, v1.y);
                *(__half2*)(Ch + base0) = h0;
                *(__half2*)(Ch + base1) = h1;
            }
        }
    }
}

// ---------------------------------------------------------------------------
// Window attention via mma.sync (proven R13 kernel). One warp per
// (window, head); 4 warps/block; register softmax; P in registers.
// ---------------------------------------------------------------------------
#define AW_WARP_H 7168
#define AW_SMEM  (4 * AW_WARP_H * 2)

__global__ __launch_bounds__(128, 2) void window_attn_kernel(
    const __half* __restrict__ qkv, __half* __restrict__ o)
{
    extern __shared__ __half sbuf[];
    const int tid = threadIdx.x;
    const int wid = tid >> 5, lane = tid & 31;
    const int w = blockIdx.x >> 1;
    const int h = ((blockIdx.x & 1) << 2) + wid;
    const int t0 = w * WIN;

    __half* sQ  = sbuf + wid * AW_WARP_H;
    __half* sK  = sQ + 2304;
    __half* sVT = sQ + 4608;

    const int gid = lane >> 2, ctid = lane & 3;
    const int mat = lane >> 3, rin = lane & 7;

#pragma unroll
    for (int i = 0; i < 8; i++) {
        const int c = lane + (i << 5);
        const int row = c >> 3, c8 = c & 7;
        const size_t gb = (size_t)(t0 + row) * DQKV + h * DH + (c8 << 3);
        *(uint4*)(sQ + row * 72 + (c8 << 3)) = *(const uint4*)(qkv + gb);
        *(uint4*)(sK + row * 72 + (c8 << 3)) = *(const uint4*)(qkv + gb + DM);
        uint4 uv = *(const uint4*)(qkv + gb + 2 * DM);
        const __half* hv = (const __half*)&uv;
#pragma unroll
        for (int d = 0; d < 8; d++)
            sVT[((c8 << 3) + d) * 40 + row] = hv[d];
    }
    __syncwarp();

    const uint32_t sQb = (uint32_t)__cvta_generic_to_shared(sQ);
    const uint32_t sKb = (uint32_t)__cvta_generic_to_shared(sK);
    const uint32_t sVb = (uint32_t)__cvta_generic_to_shared(sVT);

    uint32_t a_off[2], bk_off[2], bv_off[4];
#pragma unroll
    for (int mt = 0; mt < 2; mt++)
        a_off[mt] = sQb + ((mt * 16 + (mat & 1) * 8 + rin) * 72
                           + (mat >> 1) * 8) * 2;
#pragma unroll
    for (int np = 0; np < 2; np++)
        bk_off[np] = sKb + ((np * 16 + (mat >> 1) * 8 + rin) * 72
                            + (mat & 1) * 8) * 2;
#pragma unroll
    for (int np = 0; np < 4; np++)
        bv_off[np] = sVb + ((np * 16 + (mat >> 1) * 8 + rin) * 40
                            + (mat & 1) * 8) * 2;

    float e[2][4][4];
#pragma unroll
    for (int mt = 0; mt < 2; mt++)
#pragma unroll
        for (int nt = 0; nt < 4; nt++)
#pragma unroll
            for (int i = 0; i < 4; i++) e[mt][nt][i] = 0.0f;

#pragma unroll
    for (int ks = 0; ks < 4; ks++) {
        const uint32_t kkb = ks * 32;
        uint32_t af[2][4];
        ldsm_x4(af[0], a_off[0] + kkb);
        ldsm_x4(af[1], a_off[1] + kkb);
        uint32_t bf[4][2];
#pragma unroll
        for (int np = 0; np < 2; np++) {
            uint32_t qd[4];
            ldsm_x4(qd, bk_off[np] + kkb);
            bf[2 * np][0]     = qd[0]; bf[2 * np][1]     = qd[1];
            bf[2 * np + 1][0] = qd[2]; bf[2 * np + 1][1] = qd[3];
        }
#pragma unroll
        for (int mt = 0; mt < 2; mt++)
#pragma unroll
            for (int nt = 0; nt < 4; nt++)
                mma_f16(e[mt][nt], af[mt], bf[nt]);
    }

#pragma unroll
    for (int mt = 0; mt < 2; mt++) {
        float mxA = -1e30f, mxB = -1e30f;
#pragma unroll
        for (int nt = 0; nt < 4; nt++) {
#pragma unroll
            for (int i = 0; i < 4; i++) e[mt][nt][i] *= 0.125f;
            mxA = fmaxf(mxA, fmaxf(e[mt][nt][0], e[mt][nt][1]));
            mxB = fmaxf(mxB, fmaxf(e[mt][nt][2], e[mt][nt][3]));
        }
        mxA = fmaxf(mxA, __shfl_xor_sync(0xffffffffu, mxA, 1));
        mxA = fmaxf(mxA, __shfl_xor_sync(0xffffffffu, mxA, 2));
        mxB = fmaxf(mxB, __shfl_xor_sync(0xffffffffu, mxB, 1));
        mxB = fmaxf(mxB, __shfl_xor_sync(0xffffffffu, mxB, 2));
        float suA = 0.f, suB = 0.f;
#pragma unroll
        for (int nt = 0; nt < 4; nt++) {
            e[mt][nt][0] = __expf(e[mt][nt][0] - mxA);
            e[mt][nt][1] = __expf(e[mt][nt][1] - mxA);
            e[mt][nt][2] = __expf(e[mt][nt][2] - mxB);
            e[mt][nt][3] = __expf(e[mt][nt][3] - mxB);
            suA += e[mt][nt][0] + e[mt][nt][1];
            suB += e[mt][nt][2] + e[mt][nt][3];
        }
        suA += __shfl_xor_sync(0xffffffffu, suA, 1);
        suA += __shfl_xor_sync(0xffffffffu, suA, 2);
        suB += __shfl_xor_sync(0xffffffffu, suB, 1);
        suB += __shfl_xor_sync(0xffffffffu, suB, 2);
        const float ivA = 1.0f / suA, ivB = 1.0f / suB;
#pragma unroll
        for (int nt = 0; nt < 4; nt++) {
            e[mt][nt][0] *= ivA; e[mt][nt][1] *= ivA;
            e[mt][nt][2] *= ivB; e[mt][nt][3] *= ivB;
        }
    }

    float acc_o[2][8][4];
#pragma unroll
    for (int mt = 0; mt < 2; mt++)
#pragma unroll
        for (int nt = 0; nt < 8; nt++)
#pragma unroll
            for (int i = 0; i < 4; i++) acc_o[mt][nt][i] = 0.0f;

#pragma unroll
    for (int kt = 0; kt < 2; kt++) {
        uint32_t bv[8][2];
#pragma unroll
        for (int np = 0; np < 4; np++) {
            uint32_t qd[4];
            ldsm_x4(qd, bv_off[np] + kt * 32);
            bv[2 * np][0]     = qd[0]; bv[2 * np][1]     = qd[1];
            bv[2 * np + 1][0] = qd[2]; bv[2 * np + 1][1] = qd[3];
        }
#pragma unroll
        for (int mt = 0; mt < 2; mt++) {
            uint32_t a[4];
            a[0] = pack_h2(e[mt][2 * kt][0],     e[mt][2 * kt][1]);
            a[1] = pack_h2(e[mt][2 * kt][2],     e[mt][2 * kt][3]);
            a[2] = pack_h2(e[mt][2 * kt + 1][0], e[mt][2 * kt + 1][1]);
            a[3] = pack_h2(e[mt][2 * kt + 1][2], e[mt][2 * kt + 1][3]);
#pragma unroll
            for (int nt = 0; nt < 8; nt++)
                mma_f16(acc_o[mt][nt], a, bv[nt]);
        }
    }

    __syncwarp();
#pragma unroll
    for (int mt = 0; mt < 2; mt++)
#pragma unroll
        for (int nt = 0; nt < 8; nt++) {
            const int col = nt * 8 + 2 * ctid;
            *(__half2*)(sQ + (mt * 16 + gid) * 72 + col) =
                __floats2half2_rn(acc_o[mt][nt][0], acc_o[mt][nt][1]);
            *(__half2*)(sQ + (mt * 16 + gid + 8) * 72 + col) =
                __floats2half2_rn(acc_o[mt][nt][2], acc_o[mt][nt][3]);
        }
    __syncwarp();
#pragma unroll
    for (int i = 0; i < 8; i++) {
        const int c = lane + (i << 5);
        const int row = c >> 3, c8 = c & 7;
        *(uint4*)(o + (size_t)(t0 + row) * DM + h * DH + (c8 << 3)) =
            *(const uint4*)(sQ + row * 72 + (c8 << 3));
    }
}

// ---------------------------------------------------------------------------
// LayerNorm over a pre-summed fp16 row. One block (128 threads) per token.
// ---------------------------------------------------------------------------
__global__ __launch_bounds__(128) void ln_h_kernel(
    const __half* __restrict__ xr,
    const float* __restrict__ g, const float* __restrict__ b,
    float* __restrict__ y, __half* __restrict__ yh)
{
    const int row = blockIdx.x;
    const int tid = threadIdx.x;

    uint2 u = ((const uint2*)(xr + (size_t)row * DM))[tid];
    float2 f0 = __half22float2(*(__half2*)&u.x);
    float2 f1 = __half22float2(*(__half2*)&u.y);
    float v0 = f0.x, v1 = f0.y, v2 = f1.x, v3 = f1.y;

    __shared__ float red[4];
    float s = v0 + v1 + v2 + v3;
#pragma unroll
    for (int off = 16; off > 0; off >>= 1) s += __shfl_xor_sync(0xffffffffu, s, off);
    if ((tid & 31) == 0) red[tid >> 5] = s;
    __syncthreads();
    const float mu = (red[0] + red[1] + red[2] + red[3]) * (1.0f / DM);

    float d0 = v0 - mu, d1 = v1 - mu, d2 = v2 - mu, d3 = v3 - mu;
    float qsum = d0 * d0 + d1 * d1 + d2 * d2 + d3 * d3;
    __syncthreads();
#pragma unroll
    for (int off = 16; off > 0; off >>= 1) qsum += __shfl_xor_sync(0xffffffffu, qsum, off);
    if ((tid & 31) == 0) red[tid >> 5] = qsum;
    __syncthreads();
    const float var = (red[0] + red[1] + red[2] + red[3]) * (1.0f / DM);
    const float inv = rsqrtf(var + EPSLN);

    float4 gv = ((const float4*)g)[tid];
    float4 bv = ((const float4*)b)[tid];
    float4 out;
    out.x = d0 * inv * gv.x + bv.x;
    out.y = d1 * inv * gv.y + bv.y;
    out.z = d2 * inv * gv.z + bv.z;
    out.w = d3 * inv * gv.w + bv.w;
    if (y)
        ((float4*)(y + (size_t)row * DM))[tid] = out;
    if (yh) {
        __half2 h0 = __floats2half2_rn(out.x, out.y);
        __half2 h1 = __floats2half2_rn(out.z, out.w);
        uint2 uo;
        uo.x = *(uint32_t*)&h0;
        uo.y = *(uint32_t*)&h1;
        ((uint2*)(yh + (size_t)row * DM))[tid] = uo;
    }
}

// ---------------------------------------------------------------------------
// Launch
// ---------------------------------------------------------------------------
extern "C" void kernel_launch(void* const* d_in, const int* in_sizes, int n_in,
                              void* d_out, int out_size)
{
    (void)in_sizes; (void)n_in; (void)out_size;
    const float* x   = (const float*)d_in[0];
    const float* Wq  = (const float*)d_in[1];
    const float* bq  = (const float*)d_in[2];
    const float* Wk  = (const float*)d_in[3];
    const float* bk  = (const float*)d_in[4];
    const float* Wv  = (const float*)d_in[5];
    const float* bv  = (const float*)d_in[6];
    const float* Wo  = (const float*)d_in[7];
    const float* bo  = (const float*)d_in[8];
    const float* g1  = (const float*)d_in[9];
    const float* be1 = (const float*)d_in[10];
    const float* W1  = (const float*)d_in[11];
    const float* b1  = (const float*)d_in[12];
    const float* W2  = (const float*)d_in[13];
    const float* b2  = (const float*)d_in[14];
    const float* g2  = (const float*)d_in[15];
    const float* be2 = (const float*)d_in[16];
    float* out = (float*)d_out;

    __half *xh, *qkvh, *oh, *x1h, *hh;
    float *f32a, *bqkv;
    __half *wqkvt, *wot, *w1t, *w2t;
    cudaGetSymbolAddress((void**)&xh,    g_xh);
    cudaGetSymbolAddress((void**)&qkvh,  g_qkvh);
    cudaGetSymbolAddress((void**)&oh,    g_oh);
    cudaGetSymbolAddress((void**)&x1h,   g_x1h);
    cudaGetSymbolAddress((void**)&hh,    g_hh);
    cudaGetSymbolAddress((void**)&f32a,  g_f32a);
    cudaGetSymbolAddress((void**)&wqkvt, g_wqkvt);
    cudaGetSymbolAddress((void**)&wot,   g_wot);
    cudaGetSymbolAddress((void**)&w1t,   g_w1t);
    cudaGetSymbolAddress((void**)&w2t,   g_w2t);
    cudaGetSymbolAddress((void**)&bqkv,  g_bqkv);
    __half* resh = (__half*)f32a;   // fp16 residual-sum buffer (aliases f32a)

    cudaFuncSetAttribute(h16_gemm_kernel<8>,
                         cudaFuncAttributeMaxDynamicSharedMemorySize, GEMM_SMEM);
    cudaFuncSetAttribute(h16_gemm_kernel<32>,
                         cudaFuncAttributeMaxDynamicSharedMemorySize, GEMM_SMEM);
    cudaFuncSetAttribute(window_attn_kernel,
                         cudaFuncAttributeMaxDynamicSharedMemorySize, AW_SMEM);

    // Prep: x fp16 convert + all weight transposes + bias concat (2 launches)
    f2h_kernel<<<(TOK * DM / 4) / 256, 256>>>(x, xh);
    prep_kernel<<<3073, dim3(32, 8)>>>(Wq, Wk, Wv, Wo, W1, W2,
                                       wqkvt, wot, w1t, w2t,
                                       bq, bk, bv, bqkv);

    dim3 gQKV(DQKV / 128, TOK / 128);  // (12, 512)
    dim3 gD  (DM   / 128, TOK / 128);  // (4, 512)
    dim3 gFF (DFF  / 128, TOK / 128);  // (16, 512)

    // Fused QKV projection -> qkvh [TOK, 1536] (fp16); K=512
    h16_gemm_kernel<8><<<gQKV, 128, GEMM_SMEM>>>(xh, wqkvt, bqkv, nullptr,
                                                 nullptr, nullptr, qkvh,
                                                 TOK, DQKV, 0);

    // Block-local window attention (mma.sync)
    window_attn_kernel<<<NWIN * 2, 128, AW_SMEM>>>(qkvh, oh);

    // Output projection + residual(xh, fp16) -> resh = fp16(x + attn_out); K=512
    h16_gemm_kernel<8><<<gD, 128, GEMM_SMEM>>>(oh, wot, bo, nullptr, xh,
                                               nullptr, resh, TOK, DM, 0);

    // LN1 (fp16 in) -> x1h (fp16)
    ln_h_kernel<<<TOK, 128>>>(resh, g1, be1, nullptr, x1h);

    // FFN: W1 (K=512, ReLU) -> hh fp16
    h16_gemm_kernel<8><<<gFF, 128, GEMM_SMEM>>>(x1h, w1t, b1, nullptr, nullptr,
                                                nullptr, hh, TOK, DFF, 1);
    // W2 (K=2048) + residual(x1h) -> resh = fp16(x1 + ff_out)
    h16_gemm_kernel<32><<<gD, 128, GEMM_SMEM>>>(hh, w2t, b2, nullptr, x1h,
                                                nullptr, resh, TOK, DM, 0);

    // LN2 (fp16 in) -> output (fp32)
    ln_h_kernel<<<TOK, 128>>>(resh, g2, be2, out, nullptr);
}